// round 1
// baseline (speedup 1.0000x reference)
#include <cuda_runtime.h>
#include <cstdint>

#define N_NODESC 100000
#define N_GRAPHSC 512
#define IN_DIMC 16
#define HIDC 64
#define EPSC 1e-5f

// ---------------- device scratch (no allocations allowed) ----------------
__device__ float d_g[N_NODESC * HIDC];     // dis-scaled per-node messages
__device__ float d_accA[N_NODESC * HIDC];  // aggregation buffers (ping-pong)
__device__ float d_accB[N_NODESC * HIDC];
__device__ float d_dis[N_NODESC];
__device__ int   d_deg[N_NODESC];
__device__ float d_sumIn[IN_DIMC], d_sqIn[IN_DIMC], d_ain[IN_DIMC], d_cin[IN_DIMC];
__device__ float d_sumL[3 * HIDC], d_sqL[3 * HIDC];
__device__ float d_scl[3 * HIDC], d_shf[3 * HIDC];
__device__ float d_pool[N_GRAPHSC * HIDC];
__device__ int   d_cnt[N_GRAPHSC];

// ---------------- zero scratch accumulators ----------------
__global__ void k_zero() {
    int i = blockIdx.x * 256 + threadIdx.x;
    if (i < N_NODESC) d_deg[i] = 0;
    if (i < N_GRAPHSC * HIDC) d_pool[i] = 0.f;
    if (i < N_GRAPHSC) d_cnt[i] = 0;
    if (i < 3 * HIDC) { d_sumL[i] = 0.f; d_sqL[i] = 0.f; }
    if (i < IN_DIMC) { d_sumIn[i] = 0.f; d_sqIn[i] = 0.f; }
}

// ---------------- in-degree of real edges ----------------
__global__ void k_deg(const int* __restrict__ dst, int E) {
    int e = blockIdx.x * 256 + threadIdx.x;
    if (e < E) atomicAdd(&d_deg[dst[e]], 1);
}

// ---------------- input batchnorm stats over x [N,16] ----------------
__global__ void k_statsIn(const float* __restrict__ x) {
    int col = threadIdx.x & 15, grp = threadIdx.x >> 4;  // 16 cols x 16 groups
    float s = 0.f, q = 0.f;
    for (int row = blockIdx.x * 16 + grp; row < N_NODESC; row += gridDim.x * 16) {
        float v = x[row * IN_DIMC + col];
        s += v; q += v * v;
    }
    __shared__ float ss[16][16], qq[16][16];
    ss[grp][col] = s; qq[grp][col] = q;
    __syncthreads();
    if (grp == 0) {
        for (int j = 1; j < 16; j++) { s += ss[j][col]; q += qq[j][col]; }
        atomicAdd(&d_sumIn[col], s);
        atomicAdd(&d_sqIn[col], q);
    }
}

// ---------------- dis = rsqrt(deg+1); input BN affine fold ----------------
__global__ void k_fin1(const float* __restrict__ bng, const float* __restrict__ bnb) {
    int i = blockIdx.x * 256 + threadIdx.x;
    if (i < N_NODESC) d_dis[i] = rsqrtf((float)d_deg[i] + 1.0f);
    if (i < IN_DIMC) {
        float m = d_sumIn[i] * (1.0f / N_NODESC);
        float v = d_sqIn[i] * (1.0f / N_NODESC) - m * m;
        float a = bng[i] * rsqrtf(v + EPSC);
        d_ain[i] = a;
        d_cin[i] = bnb[i] - m * a;
    }
}

// ---------------- fused (BN+ReLU-on-input) GEMM, writes g and acc ----------------
// out[row][c] = dis[row] * sum_k T(in[row][k]) * W[k][c]
// MODE 0: T = ain[k]*x + cin[k]        (input batchnorm)
// MODE 1: T = relu((dis[row]*in + bprev[k])*scl[k] + shf[k])  (prev layer's BN+ReLU)
template <int K, int MODE>
__global__ void k_gemm(const float* __restrict__ in, const float* __restrict__ W,
                       float* __restrict__ gOut, float* __restrict__ accOut,
                       const float* __restrict__ bprev,
                       const float* __restrict__ scl, const float* __restrict__ shf) {
    __shared__ __align__(16) float Wsh[K * HIDC];
    __shared__ float insh[16 * 68];
    int tid = threadIdx.y * 16 + threadIdx.x;
    for (int idx = tid; idx < K * HIDC; idx += 256) Wsh[idx] = W[idx];

    int row = blockIdx.x * 16 + threadIdx.y;
    if (MODE == 0) {
        for (int k = threadIdx.x; k < K; k += 16) {
            float v = 0.f;
            if (row < N_NODESC) v = d_ain[k] * in[row * K + k] + d_cin[k];
            insh[threadIdx.y * 68 + k] = v;
        }
    } else {
        float dr = (row < N_NODESC) ? d_dis[row] : 0.f;
        for (int k = threadIdx.x; k < K; k += 16) {
            float v = 0.f;
            if (row < N_NODESC) {
                float u = fmaf(dr, in[row * HIDC + k], bprev[k]);
                v = fmaxf(fmaf(u, scl[k], shf[k]), 0.f);
            }
            insh[threadIdx.y * 68 + k] = v;
        }
    }
    __syncthreads();

    float a0 = 0.f, a1 = 0.f, a2 = 0.f, a3 = 0.f;
    const float4* W4 = (const float4*)Wsh;
    int base = threadIdx.y * 68;
#pragma unroll
    for (int k = 0; k < K; k++) {
        float v = insh[base + k];
        float4 w = W4[k * 16 + threadIdx.x];
        a0 = fmaf(v, w.x, a0);
        a1 = fmaf(v, w.y, a1);
        a2 = fmaf(v, w.z, a2);
        a3 = fmaf(v, w.w, a3);
    }
    if (row < N_NODESC) {
        float dr = d_dis[row];
        float4 o = make_float4(a0 * dr, a1 * dr, a2 * dr, a3 * dr);
        ((float4*)gOut)[row * 16 + threadIdx.x] = o;   // message buffer
        ((float4*)accOut)[row * 16 + threadIdx.x] = o; // acc init = self-loop term
    }
}

// ---------------- edge scatter: acc[dst] += g[src], vectorized red ----------------
__global__ void k_scatter(const int* __restrict__ src, const int* __restrict__ dst,
                          const float* __restrict__ g, float* __restrict__ acc, int E) {
    int t = blockIdx.x * 256 + threadIdx.x;
    int e = t >> 4, c = t & 15;
    if (e >= E) return;
    int s = __ldg(src + e);
    int d = __ldg(dst + e);
    float4 v = __ldg((const float4*)g + s * 16 + c);
    float* p = acc + (size_t)d * HIDC + c * 4;
    asm volatile("red.global.add.v4.f32 [%0], {%1,%2,%3,%4};"
                 :: "l"(p), "f"(v.x), "f"(v.y), "f"(v.z), "f"(v.w) : "memory");
}

// ---------------- per-layer BN stats of u = dis[i]*acc[i][c] ----------------
__global__ void k_stats(const float* __restrict__ acc, float* __restrict__ sumOut,
                        float* __restrict__ sqOut) {
    int col = threadIdx.x & 63, grp = threadIdx.x >> 6;  // 64 cols x 4 groups
    float s = 0.f, q = 0.f;
    for (int row = blockIdx.x * 4 + grp; row < N_NODESC; row += gridDim.x * 4) {
        float u = d_dis[row] * acc[row * HIDC + col];
        s += u; q += u * u;
    }
    __shared__ float ss[4][64], qq[4][64];
    ss[grp][col] = s; qq[grp][col] = q;
    __syncthreads();
    if (grp == 0) {
        s = ss[0][col] + ss[1][col] + ss[2][col] + ss[3][col];
        q = qq[0][col] + qq[1][col] + qq[2][col] + qq[3][col];
        atomicAdd(sumOut + col, s);
        atomicAdd(sqOut + col, q);
    }
}

// ---------------- fold BN into affine scl/shf per layer ----------------
__global__ void k_finbn(int layer, const float* __restrict__ b, const float* __restrict__ g,
                        const float* __restrict__ be) {
    int c = threadIdx.x;  // 64 threads
    float m = d_sumL[layer * 64 + c] * (1.0f / N_NODESC);
    float var = d_sqL[layer * 64 + c] * (1.0f / N_NODESC) - m * m;
    float s = g[c] * rsqrtf(var + EPSC);
    d_scl[layer * 64 + c] = s;
    d_shf[layer * 64 + c] = be[c] - (m + b[c]) * s;  // y = u + b; mean_y = m + b
}

// ---------------- final activation + mean-pool scatter ----------------
__global__ void k_pool(const float* __restrict__ acc, const int* __restrict__ bids,
                       const float* __restrict__ b2) {
    int t = blockIdx.x * 256 + threadIdx.x;
    int node = t >> 4, c = t & 15;
    if (node >= N_NODESC) return;
    int gph = __ldg(bids + node);
    float dr = d_dis[node];
    float4 v = __ldg((const float4*)acc + node * 16 + c);
    int cb = c * 4;
    float4 o;
    o.x = fmaxf(fmaf(fmaf(dr, v.x, b2[cb + 0]), d_scl[128 + cb + 0], d_shf[128 + cb + 0]), 0.f);
    o.y = fmaxf(fmaf(fmaf(dr, v.y, b2[cb + 1]), d_scl[128 + cb + 1], d_shf[128 + cb + 1]), 0.f);
    o.z = fmaxf(fmaf(fmaf(dr, v.z, b2[cb + 2]), d_scl[128 + cb + 2], d_shf[128 + cb + 2]), 0.f);
    o.w = fmaxf(fmaf(fmaf(dr, v.w, b2[cb + 3]), d_scl[128 + cb + 3], d_shf[128 + cb + 3]), 0.f);
    float* p = d_pool + (size_t)gph * HIDC + cb;
    asm volatile("red.global.add.v4.f32 [%0], {%1,%2,%3,%4};"
                 :: "l"(p), "f"(o.x), "f"(o.y), "f"(o.z), "f"(o.w) : "memory");
    if (c == 0) atomicAdd(&d_cnt[gph], 1);
}

// ---------------- classifier head: 512 blocks x 64 threads ----------------
__global__ void k_head(const float* __restrict__ Wc1, const float* __restrict__ bc1,
                       const float* __restrict__ Wc2, const float* __restrict__ bc2,
                       float* __restrict__ out) {
    int g = blockIdx.x, t = threadIdx.x;
    __shared__ float p[64], z[64];
    float cnt = fmaxf((float)d_cnt[g], 1.0f);
    p[t] = d_pool[g * 64 + t] / cnt;
    __syncthreads();
    float a = bc1[t];
#pragma unroll
    for (int k = 0; k < 64; k++) a = fmaf(p[k], Wc1[k * 64 + t], a);
    z[t] = fmaxf(a, 0.f);
    __syncthreads();
    if (t < 2) {
        float o = bc2[t];
#pragma unroll
        for (int k = 0; k < 64; k++) o = fmaf(z[k], Wc2[k * 2 + t], o);
        out[g * 2 + t] = o;
    }
}

// ---------------- launch ----------------
extern "C" void kernel_launch(void* const* d_in, const int* in_sizes, int n_in,
                              void* d_out, int out_size) {
    // Resolve inputs by element-count + occurrence order (robust to metadata ordering:
    // relative order within each size class is identical for both plausible orderings).
    const float *x = nullptr, *bn_in_g = nullptr, *bn_in_b = nullptr;
    const float *W0 = nullptr, *W1 = nullptr, *W2 = nullptr, *Wc1 = nullptr, *Wc2 = nullptr;
    const float *sz64[10] = {nullptr};  // b0,g0,be0,b1,g1,be1,b2,g2,be2,bc1
    const float *bc2 = nullptr;
    const int *eidx = nullptr, *bids = nullptr;
    int E = 1200000;
    int c64 = 0, c4096 = 0, c16 = 0;
    for (int i = 0; i < n_in; i++) {
        int s = in_sizes[i];
        const void* p = d_in[i];
        switch (s) {
            case 1600000: x = (const float*)p; break;
            case 2400000: eidx = (const int*)p; E = s / 2; break;
            case 100000:  bids = (const int*)p; break;
            case 16:   if (c16++ == 0) bn_in_g = (const float*)p; else bn_in_b = (const float*)p; break;
            case 1024: W0 = (const float*)p; break;
            case 4096:
                if (c4096 == 0) W1 = (const float*)p;
                else if (c4096 == 1) W2 = (const float*)p;
                else Wc1 = (const float*)p;
                c4096++; break;
            case 64:  if (c64 < 10) sz64[c64] = (const float*)p; c64++; break;
            case 128: Wc2 = (const float*)p; break;
            case 2:   bc2 = (const float*)p; break;
            default: break;
        }
    }
    const float *b0 = sz64[0], *g0 = sz64[1], *be0 = sz64[2];
    const float *b1 = sz64[3], *g1 = sz64[4], *be1 = sz64[5];
    const float *b2 = sz64[6], *g2 = sz64[7], *be2 = sz64[8];
    const float *bc1 = sz64[9];
    const int* srcA = eidx;
    const int* dstA = eidx + E;
    float* out = (float*)d_out;

    // pre-resolve device symbol addresses
    float *p_g, *p_accA, *p_accB, *p_sumL, *p_sqL, *p_scl, *p_shf;
    cudaGetSymbolAddress((void**)&p_g, d_g);
    cudaGetSymbolAddress((void**)&p_accA, d_accA);
    cudaGetSymbolAddress((void**)&p_accB, d_accB);
    cudaGetSymbolAddress((void**)&p_sumL, d_sumL);
    cudaGetSymbolAddress((void**)&p_sqL, d_sqL);
    cudaGetSymbolAddress((void**)&p_scl, d_scl);
    cudaGetSymbolAddress((void**)&p_shf, d_shf);

    const int ZGRID = (N_NODESC + 255) / 256;
    const int GEMM_GRID = (N_NODESC + 15) / 16;
    const int SC_GRID = (E * 16 + 255) / 256;
    dim3 gblk(16, 16);

    k_zero<<<ZGRID, 256>>>();
    k_deg<<<(E + 255) / 256, 256>>>(dstA, E);
    k_statsIn<<<256, 256>>>(x);
    k_fin1<<<ZGRID, 256>>>(bn_in_g, bn_in_b);

    // Layer 1: bn(x) @ W0 -> g, accA ; scatter ; stats
    k_gemm<16, 0><<<GEMM_GRID, gblk>>>(x, W0, p_g, p_accA, nullptr, nullptr, nullptr);
    k_scatter<<<SC_GRID, 256>>>(srcA, dstA, p_g, p_accA, E);
    k_stats<<<1024, 256>>>(p_accA, p_sumL + 0, p_sqL + 0);
    k_finbn<<<1, 64>>>(0, b0, g0, be0);

    // Layer 2
    k_gemm<64, 1><<<GEMM_GRID, gblk>>>(p_accA, W1, p_g, p_accB, b0, p_scl + 0, p_shf + 0);
    k_scatter<<<SC_GRID, 256>>>(srcA, dstA, p_g, p_accB, E);
    k_stats<<<1024, 256>>>(p_accB, p_sumL + 64, p_sqL + 64);
    k_finbn<<<1, 64>>>(1, b1, g1, be1);

    // Layer 3
    k_gemm<64, 1><<<GEMM_GRID, gblk>>>(p_accB, W2, p_g, p_accA, b1, p_scl + 64, p_shf + 64);
    k_scatter<<<SC_GRID, 256>>>(srcA, dstA, p_g, p_accA, E);
    k_stats<<<1024, 256>>>(p_accA, p_sumL + 128, p_sqL + 128);
    k_finbn<<<1, 64>>>(2, b2, g2, be2);

    // Pool + head
    k_pool<<<(N_NODESC * 16 + 255) / 256, 256>>>(p_accA, bids, b2);
    k_head<<<N_GRAPHSC, 64>>>(Wc1, bc1, Wc2, bc2, out);
}

// round 2
// speedup vs baseline: 1.5209x; 1.5209x over previous
#include <cuda_runtime.h>
#include <cstdint>

#define NN 100000
#define NG 512
#define IND 16
#define HID 64
#define EPS 1e-5f
#define MAXE 1200000
#define SCAN_BLOCKS 391  // ceil(NN/256)

// ---------------- device scratch ----------------
__device__ float d_g[NN * HID];     // dis-scaled per-node messages
__device__ float d_accA[NN * HID];  // aggregated (dis-scaled) node features
__device__ float d_accB[NN * HID];
__device__ float d_dis[NN];
__device__ int   d_deg[NN];
__device__ int   d_off[NN];
__device__ int   d_cur[NN];
__device__ int   d_csr[MAXE];
__device__ int   d_bsum[512];
__device__ int   d_bbase[512];
__device__ float d_sumIn[IND], d_sqIn[IND], d_ain[IND], d_cin[IND];
__device__ float d_sumL[3 * HID], d_sqL[3 * HID];
__device__ float d_scl[3 * HID], d_shf[3 * HID];
__device__ float d_pool[NG * HID];
__device__ int   d_cnt[NG];

// ---------------- f32x2 helpers ----------------
__device__ __forceinline__ unsigned long long pk2(float x) {
    unsigned long long r;
    asm("mov.b64 %0,{%1,%1};" : "=l"(r) : "f"(x));
    return r;
}
__device__ __forceinline__ void fma2(unsigned long long& d, unsigned long long a,
                                     unsigned long long b) {
    asm("fma.rn.f32x2 %0,%1,%2,%0;" : "+l"(d) : "l"(a), "l"(b));
}
__device__ __forceinline__ void unpk2(unsigned long long v, float& a, float& b) {
    asm("mov.b64 {%0,%1},%2;" : "=f"(a), "=f"(b) : "l"(v));
}

// ---------------- init ----------------
__global__ void k_zero() {
    int i = blockIdx.x * 256 + threadIdx.x;
    if (i < NN) d_deg[i] = 0;
    if (i < NG * HID) d_pool[i] = 0.f;
    if (i < NG) d_cnt[i] = 0;
    if (i < 3 * HID) { d_sumL[i] = 0.f; d_sqL[i] = 0.f; }
    if (i < IND) { d_sumIn[i] = 0.f; d_sqIn[i] = 0.f; }
}

__global__ void k_deg(const int* __restrict__ dst, int E) {
    int e = blockIdx.x * 256 + threadIdx.x;
    if (e < E) atomicAdd(&d_deg[dst[e]], 1);
}

// ---------------- input batchnorm stats over x [N,16] ----------------
__global__ void k_statsIn(const float* __restrict__ x) {
    int col = threadIdx.x & 15, grp = threadIdx.x >> 4;
    float s = 0.f, q = 0.f;
    for (int row = blockIdx.x * 16 + grp; row < NN; row += gridDim.x * 16) {
        float v = x[row * IND + col];
        s += v; q += v * v;
    }
    __shared__ float ss[16][16], qq[16][16];
    ss[grp][col] = s; qq[grp][col] = q;
    __syncthreads();
    if (grp == 0) {
        for (int j = 1; j < 16; j++) { s += ss[j][col]; q += qq[j][col]; }
        atomicAdd(&d_sumIn[col], s);
        atomicAdd(&d_sqIn[col], q);
    }
}

// ---------------- prefix scan of deg (3 kernels) ----------------
__global__ void k_scan1() {
    __shared__ int sh[256];
    int tid = threadIdx.x;
    int i = blockIdx.x * 256 + tid;
    int v = (i < NN) ? d_deg[i] : 0;
    sh[tid] = v;
    __syncthreads();
#pragma unroll
    for (int s = 1; s < 256; s <<= 1) {
        int t = (tid >= s) ? sh[tid - s] : 0;
        __syncthreads();
        sh[tid] += t;
        __syncthreads();
    }
    if (i < NN) d_off[i] = sh[tid] - v;
    if (tid == 255) d_bsum[blockIdx.x] = sh[255];
}

__global__ void k_scan2() {
    __shared__ int sh[512];
    int t = threadIdx.x;
    int v = (t < SCAN_BLOCKS) ? d_bsum[t] : 0;
    sh[t] = v;
    __syncthreads();
#pragma unroll
    for (int s = 1; s < 512; s <<= 1) {
        int u = (t >= s) ? sh[t - s] : 0;
        __syncthreads();
        sh[t] += u;
        __syncthreads();
    }
    if (t < SCAN_BLOCKS) d_bbase[t] = sh[t] - v;
}

// scan fixup + cursor reset + dis + input-BN fold
__global__ void k_scan3(const float* __restrict__ bng, const float* __restrict__ bnb) {
    int i = blockIdx.x * 256 + threadIdx.x;
    if (i < NN) {
        d_off[i] += d_bbase[i >> 8];
        d_cur[i] = 0;
        d_dis[i] = rsqrtf((float)d_deg[i] + 1.0f);
    }
    if (i < IND) {
        float m = d_sumIn[i] * (1.0f / NN);
        float v = d_sqIn[i] * (1.0f / NN) - m * m;
        float a = bng[i] * rsqrtf(v + EPS);
        d_ain[i] = a;
        d_cin[i] = bnb[i] - m * a;
    }
}

__global__ void k_fill(const int* __restrict__ src, const int* __restrict__ dst, int E) {
    int e = blockIdx.x * 256 + threadIdx.x;
    if (e >= E) return;
    int d = dst[e];
    int pos = atomicAdd(&d_cur[d], 1);
    d_csr[d_off[d] + pos] = src[e];
}

// ---------------- GEMM: g[row] = dis[row] * (T(in[row]) @ W) ----------------
// MODE 0: T = ain[k]*x + cin[k]                 (input BN)
// MODE 1: T = relu(in*scl[k] + shf[k])          (prev layer folded BN+ReLU; in is dis-scaled acc)
// 64 rows/block; thread (tx,ty) computes cols tx*4..+3 for rows ty*4..+3.
template <int K, int MODE>
__global__ void __launch_bounds__(256) k_gemm(const float* __restrict__ in,
                                              const float* __restrict__ W,
                                              float* __restrict__ gOut,
                                              const float* __restrict__ scl,
                                              const float* __restrict__ shf) {
    __shared__ __align__(16) float Wsh[K * 64];
    __shared__ __align__(16) float ins[K * 68];  // transposed [k][row], pad 68
    const int tx = threadIdx.x, ty = threadIdx.y;
    const int tid = ty * 16 + tx;
    for (int i = tid; i < K * 64; i += 256) Wsh[i] = W[i];

    const int rowBase = blockIdx.x * 64;
    const int kk = tid & (K - 1);  // constant per thread since 256 % K == 0
    float t_a, t_c;
    if (MODE == 0) { t_a = d_ain[kk]; t_c = d_cin[kk]; }
    else           { t_a = scl[kk];   t_c = shf[kk]; }
    const int SH = (K == 16) ? 4 : 6;
    for (int i = tid; i < 64 * K; i += 256) {
        int rl = i >> SH;
        int row = rowBase + rl;
        float v = 0.f;
        if (row < NN) {
            float u = in[row * K + kk];
            if (MODE == 0) v = fmaf(t_a, u, t_c);
            else           v = fmaxf(fmaf(u, t_a, t_c), 0.f);
        }
        ins[kk * 68 + rl] = v;
    }
    __syncthreads();

    unsigned long long a01[4] = {0ull, 0ull, 0ull, 0ull};
    unsigned long long a23[4] = {0ull, 0ull, 0ull, 0ull};
#pragma unroll
    for (int k = 0; k < K; k++) {
        ulonglong2 w = *(const ulonglong2*)(Wsh + k * 64 + tx * 4);
        float4 v = *(const float4*)(ins + k * 68 + ty * 4);
        unsigned long long v0 = pk2(v.x), v1 = pk2(v.y), v2 = pk2(v.z), v3 = pk2(v.w);
        fma2(a01[0], v0, w.x); fma2(a23[0], v0, w.y);
        fma2(a01[1], v1, w.x); fma2(a23[1], v1, w.y);
        fma2(a01[2], v2, w.x); fma2(a23[2], v2, w.y);
        fma2(a01[3], v3, w.x); fma2(a23[3], v3, w.y);
    }
#pragma unroll
    for (int r = 0; r < 4; r++) {
        int row = rowBase + ty * 4 + r;
        if (row < NN) {
            float dr = d_dis[row];
            float x0, x1, x2, x3;
            unpk2(a01[r], x0, x1);
            unpk2(a23[r], x2, x3);
            ((float4*)gOut)[row * 16 + tx] = make_float4(x0 * dr, x1 * dr, x2 * dr, x3 * dr);
        }
    }
}

// ---------------- CSR aggregation + dis-scale + fused BN stats ----------------
// acc[n] = dis[n] * (g[n] + sum_{s in N(n)} g[s]); stats over acc.
__global__ void __launch_bounds__(256) k_agg(const float4* __restrict__ g4,
                                             float4* __restrict__ acc4,
                                             float* __restrict__ sumOut,
                                             float* __restrict__ sqOut) {
    __shared__ float ssum[64], ssq[64];
    const int tx = threadIdx.x, ty = threadIdx.y;
    const int tid = ty * 16 + tx;
    if (tid < 64) { ssum[tid] = 0.f; ssq[tid] = 0.f; }
    __syncthreads();

    float psx = 0.f, psy = 0.f, psz = 0.f, psw = 0.f;
    float pqx = 0.f, pqy = 0.f, pqz = 0.f, pqw = 0.f;
    const int base = blockIdx.x * 64 + ty * 4;
#pragma unroll
    for (int r = 0; r < 4; r++) {
        int n = base + r;
        if (n >= NN) break;
        float4 a = __ldg(g4 + (size_t)n * 16 + tx);  // self-loop term
        int beg = d_off[n];
        int cnt = d_deg[n];
        int e = 0;
        for (; e + 4 <= cnt; e += 4) {
            int s0 = __ldg(d_csr + beg + e);
            int s1 = __ldg(d_csr + beg + e + 1);
            int s2 = __ldg(d_csr + beg + e + 2);
            int s3 = __ldg(d_csr + beg + e + 3);
            float4 v0 = __ldg(g4 + (size_t)s0 * 16 + tx);
            float4 v1 = __ldg(g4 + (size_t)s1 * 16 + tx);
            float4 v2 = __ldg(g4 + (size_t)s2 * 16 + tx);
            float4 v3 = __ldg(g4 + (size_t)s3 * 16 + tx);
            a.x += (v0.x + v1.x) + (v2.x + v3.x);
            a.y += (v0.y + v1.y) + (v2.y + v3.y);
            a.z += (v0.z + v1.z) + (v2.z + v3.z);
            a.w += (v0.w + v1.w) + (v2.w + v3.w);
        }
        for (; e < cnt; e++) {
            int s = __ldg(d_csr + beg + e);
            float4 v = __ldg(g4 + (size_t)s * 16 + tx);
            a.x += v.x; a.y += v.y; a.z += v.z; a.w += v.w;
        }
        float dr = d_dis[n];
        a.x *= dr; a.y *= dr; a.z *= dr; a.w *= dr;
        acc4[(size_t)n * 16 + tx] = a;
        psx += a.x; psy += a.y; psz += a.z; psw += a.w;
        pqx += a.x * a.x; pqy += a.y * a.y; pqz += a.z * a.z; pqw += a.w * a.w;
    }
    int c0 = tx * 4;
    atomicAdd(&ssum[c0 + 0], psx); atomicAdd(&ssq[c0 + 0], pqx);
    atomicAdd(&ssum[c0 + 1], psy); atomicAdd(&ssq[c0 + 1], pqy);
    atomicAdd(&ssum[c0 + 2], psz); atomicAdd(&ssq[c0 + 2], pqz);
    atomicAdd(&ssum[c0 + 3], psw); atomicAdd(&ssq[c0 + 3], pqw);
    __syncthreads();
    if (tid < 64) {
        atomicAdd(sumOut + tid, ssum[tid]);
        atomicAdd(sqOut + tid, ssq[tid]);
    }
}

// ---------------- fold BN into affine scl/shf per layer (bias b cancels) ----------------
__global__ void k_finbn(int layer, const float* __restrict__ g, const float* __restrict__ be) {
    int c = threadIdx.x;  // 64 threads
    float m = d_sumL[layer * 64 + c] * (1.0f / NN);
    float var = d_sqL[layer * 64 + c] * (1.0f / NN) - m * m;
    float s = g[c] * rsqrtf(var + EPS);
    d_scl[layer * 64 + c] = s;
    d_shf[layer * 64 + c] = be[c] - m * s;
}

// ---------------- final activation + mean-pool scatter ----------------
__global__ void k_pool(const float4* __restrict__ acc4, const int* __restrict__ bids) {
    int t = blockIdx.x * 256 + threadIdx.x;
    int node = t >> 4, c = t & 15;
    if (node >= NN) return;
    int gph = __ldg(bids + node);
    float4 v = __ldg(acc4 + (size_t)node * 16 + c);
    int cb = c * 4;
    float4 o;
    o.x = fmaxf(fmaf(v.x, d_scl[128 + cb + 0], d_shf[128 + cb + 0]), 0.f);
    o.y = fmaxf(fmaf(v.y, d_scl[128 + cb + 1], d_shf[128 + cb + 1]), 0.f);
    o.z = fmaxf(fmaf(v.z, d_scl[128 + cb + 2], d_shf[128 + cb + 2]), 0.f);
    o.w = fmaxf(fmaf(v.w, d_scl[128 + cb + 3], d_shf[128 + cb + 3]), 0.f);
    float* p = d_pool + (size_t)gph * HID + cb;
    asm volatile("red.global.add.v4.f32 [%0], {%1,%2,%3,%4};"
                 :: "l"(p), "f"(o.x), "f"(o.y), "f"(o.z), "f"(o.w) : "memory");
    if (c == 0) atomicAdd(&d_cnt[gph], 1);
}

// ---------------- classifier head ----------------
__global__ void k_head(const float* __restrict__ Wc1, const float* __restrict__ bc1,
                       const float* __restrict__ Wc2, const float* __restrict__ bc2,
                       float* __restrict__ out) {
    int g = blockIdx.x, t = threadIdx.x;
    __shared__ float p[64], z[64];
    float cnt = fmaxf((float)d_cnt[g], 1.0f);
    p[t] = d_pool[g * 64 + t] / cnt;
    __syncthreads();
    float a = bc1[t];
#pragma unroll
    for (int k = 0; k < 64; k++) a = fmaf(p[k], Wc1[k * 64 + t], a);
    z[t] = fmaxf(a, 0.f);
    __syncthreads();
    if (t < 2) {
        float o = bc2[t];
#pragma unroll
        for (int k = 0; k < 64; k++) o = fmaf(z[k], Wc2[k * 2 + t], o);
        out[g * 2 + t] = o;
    }
}

// ---------------- launch ----------------
extern "C" void kernel_launch(void* const* d_in, const int* in_sizes, int n_in,
                              void* d_out, int out_size) {
    const float *x = nullptr, *bn_in_g = nullptr, *bn_in_b = nullptr;
    const float *W0 = nullptr, *W1 = nullptr, *W2 = nullptr, *Wc1 = nullptr, *Wc2 = nullptr;
    const float *sz64[10] = {nullptr};
    const float *bc2 = nullptr;
    const int *eidx = nullptr, *bids = nullptr;
    int E = 1200000;
    int c64 = 0, c4096 = 0, c16 = 0;
    for (int i = 0; i < n_in; i++) {
        int s = in_sizes[i];
        const void* p = d_in[i];
        switch (s) {
            case 1600000: x = (const float*)p; break;
            case 2400000: eidx = (const int*)p; E = s / 2; break;
            case 100000:  bids = (const int*)p; break;
            case 16:   if (c16++ == 0) bn_in_g = (const float*)p; else bn_in_b = (const float*)p; break;
            case 1024: W0 = (const float*)p; break;
            case 4096:
                if (c4096 == 0) W1 = (const float*)p;
                else if (c4096 == 1) W2 = (const float*)p;
                else Wc1 = (const float*)p;
                c4096++; break;
            case 64:  if (c64 < 10) sz64[c64] = (const float*)p; c64++; break;
            case 128: Wc2 = (const float*)p; break;
            case 2:   bc2 = (const float*)p; break;
            default: break;
        }
    }
    // order: b0,g0,be0,b1,g1,be1,b2,g2,be2,bc1 (biases b* unused — folded out)
    const float *g0 = sz64[1], *be0 = sz64[2];
    const float *g1 = sz64[4], *be1 = sz64[5];
    const float *g2 = sz64[7], *be2 = sz64[8];
    const float *bc1 = sz64[9];
    const int* srcA = eidx;
    const int* dstA = eidx + E;
    float* out = (float*)d_out;

    float *p_g, *p_accA, *p_accB, *p_sumL, *p_sqL, *p_scl, *p_shf;
    cudaGetSymbolAddress((void**)&p_g, d_g);
    cudaGetSymbolAddress((void**)&p_accA, d_accA);
    cudaGetSymbolAddress((void**)&p_accB, d_accB);
    cudaGetSymbolAddress((void**)&p_sumL, d_sumL);
    cudaGetSymbolAddress((void**)&p_sqL, d_sqL);
    cudaGetSymbolAddress((void**)&p_scl, d_scl);
    cudaGetSymbolAddress((void**)&p_shf, d_shf);

    const int ZG = SCAN_BLOCKS;
    const int EG = (E + 255) / 256;
    const int GG = (NN + 63) / 64;  // 1563
    dim3 gblk(16, 16);

    k_zero<<<ZG, 256>>>();
    k_deg<<<EG, 256>>>(dstA, E);
    k_statsIn<<<256, 256>>>(x);
    k_scan1<<<ZG, 256>>>();
    k_scan2<<<1, 512>>>();
    k_scan3<<<ZG, 256>>>(bn_in_g, bn_in_b);
    k_fill<<<EG, 256>>>(srcA, dstA, E);

    // Layer 1
    k_gemm<16, 0><<<GG, gblk>>>(x, W0, p_g, nullptr, nullptr);
    k_agg<<<GG, gblk>>>((const float4*)p_g, (float4*)p_accA, p_sumL + 0, p_sqL + 0);
    k_finbn<<<1, 64>>>(0, g0, be0);

    // Layer 2
    k_gemm<64, 1><<<GG, gblk>>>(p_accA, W1, p_g, p_scl + 0, p_shf + 0);
    k_agg<<<GG, gblk>>>((const float4*)p_g, (float4*)p_accB, p_sumL + 64, p_sqL + 64);
    k_finbn<<<1, 64>>>(1, g1, be1);

    // Layer 3
    k_gemm<64, 1><<<GG, gblk>>>(p_accB, W2, p_g, p_scl + 64, p_shf + 64);
    k_agg<<<GG, gblk>>>((const float4*)p_g, (float4*)p_accA, p_sumL + 128, p_sqL + 128);
    k_finbn<<<1, 64>>>(2, g2, be2);

    // Pool + head
    k_pool<<<(NN * 16 + 255) / 256, 256>>>((const float4*)p_accA, bids);
    k_head<<<NG, 64>>>(Wc1, bc1, Wc2, bc2, out);
}

// round 5
// speedup vs baseline: 1.5655x; 1.0293x over previous
#include <cuda_runtime.h>
#include <cstdint>

#define NN 100000
#define NG 512
#define IND 16
#define HID 64
#define EPS 1e-5f
#define MAXE 1200000
#define SCAN_BLOCKS 391  // ceil(NN/256)

// ---------------- device scratch ----------------
__device__ float d_g[NN * HID];     // dis-scaled per-node messages
__device__ float d_accA[NN * HID];
__device__ float d_accB[NN * HID];
__device__ float d_dis[NN];
__device__ int   d_deg[NN];
__device__ int   d_off[NN];
__device__ int   d_cur[NN];
__device__ int   d_csr[MAXE];
__device__ int   d_bsum[512];
__device__ int   d_bbase[512];
__device__ float d_sumIn[IND], d_sqIn[IND], d_ain[IND], d_cin[IND];
__device__ float d_sumL[3 * HID], d_sqL[3 * HID];
__device__ float d_pool[NG * HID];
__device__ int   d_cnt[NG];

// ---------------- f32x2 helpers ----------------
__device__ __forceinline__ unsigned long long pk2(float x) {
    unsigned long long r;
    asm("mov.b64 %0,{%1,%1};" : "=l"(r) : "f"(x));
    return r;
}
__device__ __forceinline__ void fma2(unsigned long long& d, unsigned long long a,
                                     unsigned long long b) {
    asm("fma.rn.f32x2 %0,%1,%2,%0;" : "+l"(d) : "l"(a), "l"(b));
}
__device__ __forceinline__ void unpk2(unsigned long long v, float& a, float& b) {
    asm("mov.b64 {%0,%1},%2;" : "=f"(a), "=f"(b) : "l"(v));
}

// ---------------- init ----------------
__global__ void k_zero() {
    int i = blockIdx.x * 256 + threadIdx.x;
    if (i < NN) d_deg[i] = 0;
    if (i < NG * HID) d_pool[i] = 0.f;
    if (i < NG) d_cnt[i] = 0;
    if (i < 3 * HID) { d_sumL[i] = 0.f; d_sqL[i] = 0.f; }
    if (i < IND) { d_sumIn[i] = 0.f; d_sqIn[i] = 0.f; }
}

__global__ void k_deg(const int* __restrict__ dst, int E) {
    int e = blockIdx.x * 256 + threadIdx.x;
    if (e < E) atomicAdd(&d_deg[dst[e]], 1);
}

// ---------------- input batchnorm stats over x [N,16] ----------------
__global__ void k_statsIn(const float* __restrict__ x) {
    int col = threadIdx.x & 15, grp = threadIdx.x >> 4;
    float s = 0.f, q = 0.f;
    for (int row = blockIdx.x * 16 + grp; row < NN; row += gridDim.x * 16) {
        float v = x[row * IND + col];
        s += v; q += v * v;
    }
    __shared__ float ss[16][16], qq[16][16];
    ss[grp][col] = s; qq[grp][col] = q;
    __syncthreads();
    if (grp == 0) {
        for (int j = 1; j < 16; j++) { s += ss[j][col]; q += qq[j][col]; }
        atomicAdd(&d_sumIn[col], s);
        atomicAdd(&d_sqIn[col], q);
    }
}

// ---------------- dis + input-BN fold (runs on side stream) ----------------
__global__ void k_fin(const float* __restrict__ bng, const float* __restrict__ bnb) {
    int i = blockIdx.x * 256 + threadIdx.x;
    if (i < NN) d_dis[i] = rsqrtf((float)d_deg[i] + 1.0f);
    if (i < IND) {
        float m = d_sumIn[i] * (1.0f / NN);
        float v = d_sqIn[i] * (1.0f / NN) - m * m;
        float a = bng[i] * rsqrtf(v + EPS);
        d_ain[i] = a;
        d_cin[i] = bnb[i] - m * a;
    }
}

// ---------------- prefix scan of deg ----------------
__global__ void k_scan1() {
    __shared__ int sh[256];
    int tid = threadIdx.x;
    int i = blockIdx.x * 256 + tid;
    int v = (i < NN) ? d_deg[i] : 0;
    sh[tid] = v;
    __syncthreads();
#pragma unroll
    for (int s = 1; s < 256; s <<= 1) {
        int t = (tid >= s) ? sh[tid - s] : 0;
        __syncthreads();
        sh[tid] += t;
        __syncthreads();
    }
    if (i < NN) d_off[i] = sh[tid] - v;
    if (tid == 255) d_bsum[blockIdx.x] = sh[255];
}

__global__ void k_scan2() {
    __shared__ int sh[512];
    int t = threadIdx.x;
    int v = (t < SCAN_BLOCKS) ? d_bsum[t] : 0;
    sh[t] = v;
    __syncthreads();
#pragma unroll
    for (int s = 1; s < 512; s <<= 1) {
        int u = (t >= s) ? sh[t - s] : 0;
        __syncthreads();
        sh[t] += u;
        __syncthreads();
    }
    if (t < SCAN_BLOCKS) d_bbase[t] = sh[t] - v;
}

__global__ void k_scan3() {
    int i = blockIdx.x * 256 + threadIdx.x;
    if (i < NN) {
        d_off[i] += d_bbase[i >> 8];
        d_cur[i] = 0;
    }
}

__global__ void k_fill(const int* __restrict__ src, const int* __restrict__ dst, int E) {
    int e = blockIdx.x * 256 + threadIdx.x;
    if (e >= E) return;
    int d = dst[e];
    int pos = atomicAdd(&d_cur[d], 1);
    d_csr[d_off[d] + pos] = src[e];
}

// ---------------- GEMM: g[row] = dis[row] * (T(in[row]) @ W) ----------------
// 128 threads/block, 128 rows/block, each thread computes 8 rows x 8 cols.
// Split-K staging: CHUNK=32 (or 16) rows of transposed input at a time.
// MODE 0: T = ain[k]*x + cin[k]
// MODE 1: T = relu(in*scl[k] + shf[k]), scl/shf computed per-block from stats.
template <int K, int MODE>
__global__ void __launch_bounds__(128) k_gemm(const float* __restrict__ in,
                                              const float* __restrict__ W,
                                              float* __restrict__ gOut,
                                              const float* __restrict__ sumL,
                                              const float* __restrict__ sqL,
                                              const float* __restrict__ gam,
                                              const float* __restrict__ bet) {
    constexpr int CHUNK = (K < 32) ? K : 32;
    constexpr int NCH = K / CHUNK;
    constexpr int SH = (CHUNK == 16) ? 4 : 5;
    __shared__ __align__(16) float Wsh[K * 64];
    __shared__ __align__(16) float ins[CHUNK * 132];
    __shared__ float sA[64], sC[64];
    const int tid = threadIdx.x;
    const int c0 = (tid & 7) * 8;
    const int r0 = (tid >> 3) * 8;

    for (int i = tid; i < K * 64; i += 128) Wsh[i] = W[i];
    if (MODE == 0) {
        if (tid < K) { sA[tid] = d_ain[tid]; sC[tid] = d_cin[tid]; }
    } else {
        if (tid < 64) {
            float m = sumL[tid] * (1.0f / NN);
            float var = sqL[tid] * (1.0f / NN) - m * m;
            float s = gam[tid] * rsqrtf(var + EPS);
            sA[tid] = s;
            sC[tid] = bet[tid] - m * s;
        }
    }

    const int rowBase = blockIdx.x * 128;
    const int kk = tid & (CHUNK - 1);
    unsigned long long acc[8][4];
#pragma unroll
    for (int r = 0; r < 8; r++)
#pragma unroll
        for (int c = 0; c < 4; c++) acc[r][c] = 0ull;

    for (int kc = 0; kc < NCH; kc++) {
        __syncthreads();  // sA ready (iter 0); prev chunk's reads done (iter>0)
        const int kg = kc * CHUNK + kk;
        const float t_a = sA[kg], t_c = sC[kg];
        for (int i = tid; i < 128 * CHUNK; i += 128) {
            int rl = i >> SH;
            int row = rowBase + rl;
            float v = 0.f;
            if (row < NN) {
                float u = in[(size_t)row * K + kg];
                if (MODE == 0) v = fmaf(t_a, u, t_c);
                else           v = fmaxf(fmaf(u, t_a, t_c), 0.f);
            }
            ins[kk * 132 + rl] = v;
        }
        __syncthreads();
#pragma unroll
        for (int k = 0; k < CHUNK; k++) {
            const float* wrow = Wsh + (kc * CHUNK + k) * 64;
            ulonglong2 wa = *(const ulonglong2*)(wrow + c0);
            ulonglong2 wb = *(const ulonglong2*)(wrow + c0 + 4);
            const float* vrow = ins + k * 132;
            float4 va = *(const float4*)(vrow + r0);
            float4 vb = *(const float4*)(vrow + r0 + 4);
            unsigned long long p[8] = {pk2(va.x), pk2(va.y), pk2(va.z), pk2(va.w),
                                       pk2(vb.x), pk2(vb.y), pk2(vb.z), pk2(vb.w)};
#pragma unroll
            for (int r = 0; r < 8; r++) {
                fma2(acc[r][0], p[r], wa.x);
                fma2(acc[r][1], p[r], wa.y);
                fma2(acc[r][2], p[r], wb.x);
                fma2(acc[r][3], p[r], wb.y);
            }
        }
    }

#pragma unroll
    for (int r = 0; r < 8; r++) {
        int row = rowBase + r0 + r;
        if (row < NN) {
            float dr = d_dis[row];
            float f0, f1, f2, f3, f4, f5, f6, f7;
            unpk2(acc[r][0], f0, f1);
            unpk2(acc[r][1], f2, f3);
            unpk2(acc[r][2], f4, f5);
            unpk2(acc[r][3], f6, f7);
            *(float4*)(gOut + (size_t)row * 64 + c0) =
                make_float4(f0 * dr, f1 * dr, f2 * dr, f3 * dr);
            *(float4*)(gOut + (size_t)row * 64 + c0 + 4) =
                make_float4(f4 * dr, f5 * dr, f6 * dr, f7 * dr);
        }
    }
}

// ---------------- CSR aggregation + dis-scale + fused BN stats ----------------
__global__ void __launch_bounds__(256) k_agg(const float4* __restrict__ g4,
                                             float4* __restrict__ acc4,
                                             float* __restrict__ sumOut,
                                             float* __restrict__ sqOut) {
    __shared__ float ssum[64], ssq[64];
    const int tx = threadIdx.x, ty = threadIdx.y;
    const int tid = ty * 16 + tx;
    if (tid < 64) { ssum[tid] = 0.f; ssq[tid] = 0.f; }
    __syncthreads();

    float psx = 0.f, psy = 0.f, psz = 0.f, psw = 0.f;
    float pqx = 0.f, pqy = 0.f, pqz = 0.f, pqw = 0.f;
    const int base = blockIdx.x * 64 + ty * 4;
#pragma unroll
    for (int r = 0; r < 4; r++) {
        int n = base + r;
        if (n >= NN) break;
        float4 a = __ldg(g4 + (size_t)n * 16 + tx);  // self-loop term
        int beg = d_off[n];
        int cnt = d_deg[n];
        int e = 0;
        for (; e + 4 <= cnt; e += 4) {
            int s0 = __ldg(d_csr + beg + e);
            int s1 = __ldg(d_csr + beg + e + 1);
            int s2 = __ldg(d_csr + beg + e + 2);
            int s3 = __ldg(d_csr + beg + e + 3);
            float4 v0 = __ldg(g4 + (size_t)s0 * 16 + tx);
            float4 v1 = __ldg(g4 + (size_t)s1 * 16 + tx);
            float4 v2 = __ldg(g4 + (size_t)s2 * 16 + tx);
            float4 v3 = __ldg(g4 + (size_t)s3 * 16 + tx);
            a.x += (v0.x + v1.x) + (v2.x + v3.x);
            a.y += (v0.y + v1.y) + (v2.y + v3.y);
            a.z += (v0.z + v1.z) + (v2.z + v3.z);
            a.w += (v0.w + v1.w) + (v2.w + v3.w);
        }
        for (; e < cnt; e++) {
            int s = __ldg(d_csr + beg + e);
            float4 v = __ldg(g4 + (size_t)s * 16 + tx);
            a.x += v.x; a.y += v.y; a.z += v.z; a.w += v.w;
        }
        float dr = d_dis[n];
        a.x *= dr; a.y *= dr; a.z *= dr; a.w *= dr;
        acc4[(size_t)n * 16 + tx] = a;
        psx += a.x; psy += a.y; psz += a.z; psw += a.w;
        pqx += a.x * a.x; pqy += a.y * a.y; pqz += a.z * a.z; pqw += a.w * a.w;
    }
    int c0 = tx * 4;
    atomicAdd(&ssum[c0 + 0], psx); atomicAdd(&ssq[c0 + 0], pqx);
    atomicAdd(&ssum[c0 + 1], psy); atomicAdd(&ssq[c0 + 1], pqy);
    atomicAdd(&ssum[c0 + 2], psz); atomicAdd(&ssq[c0 + 2], pqz);
    atomicAdd(&ssum[c0 + 3], psw); atomicAdd(&ssq[c0 + 3], pqw);
    __syncthreads();
    if (tid < 64) {
        atomicAdd(sumOut + tid, ssum[tid]);
        atomicAdd(sqOut + tid, ssq[tid]);
    }
}

// ---------------- final activation + mean-pool scatter (fused layer-3 BN fold) ----
__global__ void k_pool(const float4* __restrict__ acc4, const int* __restrict__ bids,
                       const float* __restrict__ sumL, const float* __restrict__ sqL,
                       const float* __restrict__ gam, const float* __restrict__ bet) {
    __shared__ float sA[64], sC[64];
    int tid = threadIdx.x;
    if (tid < 64) {
        float m = sumL[tid] * (1.0f / NN);
        float var = sqL[tid] * (1.0f / NN) - m * m;
        float s = gam[tid] * rsqrtf(var + EPS);
        sA[tid] = s;
        sC[tid] = bet[tid] - m * s;
    }
    __syncthreads();
    int t = blockIdx.x * 256 + tid;
    int node = t >> 4, c = t & 15;
    if (node >= NN) return;
    int gph = __ldg(bids + node);
    float4 v = __ldg(acc4 + (size_t)node * 16 + c);
    int cb = c * 4;
    float4 o;
    o.x = fmaxf(fmaf(v.x, sA[cb + 0], sC[cb + 0]), 0.f);
    o.y = fmaxf(fmaf(v.y, sA[cb + 1], sC[cb + 1]), 0.f);
    o.z = fmaxf(fmaf(v.z, sA[cb + 2], sC[cb + 2]), 0.f);
    o.w = fmaxf(fmaf(v.w, sA[cb + 3], sC[cb + 3]), 0.f);
    float* p = d_pool + (size_t)gph * HID + cb;
    asm volatile("red.global.add.v4.f32 [%0], {%1,%2,%3,%4};"
                 :: "l"(p), "f"(o.x), "f"(o.y), "f"(o.z), "f"(o.w) : "memory");
    if (c == 0) atomicAdd(&d_cnt[gph], 1);
}

// ---------------- classifier head ----------------
__global__ void k_head(const float* __restrict__ Wc1, const float* __restrict__ bc1,
                       const float* __restrict__ Wc2, const float* __restrict__ bc2,
                       float* __restrict__ out) {
    int g = blockIdx.x, t = threadIdx.x;
    __shared__ float p[64], z[64];
    float cnt = fmaxf((float)d_cnt[g], 1.0f);
    p[t] = d_pool[g * 64 + t] / cnt;
    __syncthreads();
    float a = bc1[t];
#pragma unroll
    for (int k = 0; k < 64; k++) a = fmaf(p[k], Wc1[k * 64 + t], a);
    z[t] = fmaxf(a, 0.f);
    __syncthreads();
    if (t < 2) {
        float o = bc2[t];
#pragma unroll
        for (int k = 0; k < 64; k++) o = fmaf(z[k], Wc2[k * 2 + t], o);
        out[g * 2 + t] = o;
    }
}

// ---------------- launch ----------------
extern "C" void kernel_launch(void* const* d_in, const int* in_sizes, int n_in,
                              void* d_out, int out_size) {
    const float *x = nullptr, *bn_in_g = nullptr, *bn_in_b = nullptr;
    const float *W0 = nullptr, *W1 = nullptr, *W2 = nullptr, *Wc1 = nullptr, *Wc2 = nullptr;
    const float *sz64[10] = {nullptr};
    const float *bc2 = nullptr;
    const int *eidx = nullptr, *bids = nullptr;
    int E = 1200000;
    int c64 = 0, c4096 = 0, c16 = 0;
    for (int i = 0; i < n_in; i++) {
        int s = in_sizes[i];
        const void* p = d_in[i];
        switch (s) {
            case 1600000: x = (const float*)p; break;
            case 2400000: eidx = (const int*)p; E = s / 2; break;
            case 100000:  bids = (const int*)p; break;
            case 16:   if (c16++ == 0) bn_in_g = (const float*)p; else bn_in_b = (const float*)p; break;
            case 1024: W0 = (const float*)p; break;
            case 4096:
                if (c4096 == 0) W1 = (const float*)p;
                else if (c4096 == 1) W2 = (const float*)p;
                else Wc1 = (const float*)p;
                c4096++; break;
            case 64:  if (c64 < 10) sz64[c64] = (const float*)p; c64++; break;
            case 128: Wc2 = (const float*)p; break;
            case 2:   bc2 = (const float*)p; break;
            default: break;
        }
    }
    // order: b0,g0,be0,b1,g1,be1,b2,g2,be2,bc1 (biases b* folded out algebraically)
    const float *g0 = sz64[1], *be0 = sz64[2];
    const float *g1 = sz64[4], *be1 = sz64[5];
    const float *g2 = sz64[7], *be2 = sz64[8];
    const float *bc1 = sz64[9];
    const int* srcA = eidx;
    const int* dstA = eidx + E;
    float* out = (float*)d_out;

    float *p_g, *p_accA, *p_accB, *p_sumL, *p_sqL;
    cudaGetSymbolAddress((void**)&p_g, d_g);
    cudaGetSymbolAddress((void**)&p_accA, d_accA);
    cudaGetSymbolAddress((void**)&p_accB, d_accB);
    cudaGetSymbolAddress((void**)&p_sumL, d_sumL);
    cudaGetSymbolAddress((void**)&p_sqL, d_sqL);

    // Lazy one-time resources (created on the first, non-captured, correctness
    // call; behavior is identical on every call — pure fork/join plumbing).
    static cudaStream_t s2 = nullptr;
    static cudaEvent_t ev1 = nullptr, ev2 = nullptr;
    if (!s2) {
        cudaStreamCreateWithFlags(&s2, cudaStreamNonBlocking);
        cudaEventCreateWithFlags(&ev1, cudaEventDisableTiming);
        cudaEventCreateWithFlags(&ev2, cudaEventDisableTiming);
    }

    const int ZG = SCAN_BLOCKS;
    const int EG = (E + 255) / 256;
    const int GG = (NN + 127) / 128;  // 782 gemm blocks
    const int AG = (NN + 63) / 64;    // 1563 agg blocks
    dim3 ablk(16, 16);

    k_zero<<<ZG, 256>>>();
    k_deg<<<EG, 256>>>(dstA, E);

    // fork: BN-stats + input-fold + layer-1 GEMM overlap the CSR build
    cudaEventRecord(ev1, 0);
    cudaStreamWaitEvent(s2, ev1, 0);
    k_statsIn<<<256, 256, 0, s2>>>(x);
    k_fin<<<ZG, 256, 0, s2>>>(bn_in_g, bn_in_b);
    k_gemm<16, 0><<<GG, 128, 0, s2>>>(x, W0, p_g, nullptr, nullptr, nullptr, nullptr);
    cudaEventRecord(ev2, s2);

    k_scan1<<<ZG, 256>>>();
    k_scan2<<<1, 512>>>();
    k_scan3<<<ZG, 256>>>();
    k_fill<<<EG, 256>>>(srcA, dstA, E);

    cudaStreamWaitEvent(0, ev2, 0);  // join

    // Layer 1 aggregation
    k_agg<<<AG, ablk>>>((const float4*)p_g, (float4*)p_accA, p_sumL + 0, p_sqL + 0);
    // Layer 2
    k_gemm<64, 1><<<GG, 128>>>(p_accA, W1, p_g, p_sumL + 0, p_sqL + 0, g0, be0);
    k_agg<<<AG, ablk>>>((const float4*)p_g, (float4*)p_accB, p_sumL + 64, p_sqL + 64);
    // Layer 3
    k_gemm<64, 1><<<GG, 128>>>(p_accB, W2, p_g, p_sumL + 64, p_sqL + 64, g1, be1);
    k_agg<<<AG, ablk>>>((const float4*)p_g, (float4*)p_accA, p_sumL + 128, p_sqL + 128);

    // Pool (fused layer-3 BN fold) + head
    k_pool<<<(NN * 16 + 255) / 256, 256>>>((const float4*)p_accA, bids,
                                           p_sumL + 128, p_sqL + 128, g2, be2);
    k_head<<<NG, 64>>>(Wc1, bc1, Wc2, bc2, out);
}

// round 6
// speedup vs baseline: 1.7665x; 1.1284x over previous
#include <cuda_runtime.h>
#include <cuda_fp16.h>
#include <cstdint>

#define NN 100000
#define NG 512
#define IND 16
#define HID 64
#define EPS 1e-5f
#define MAXE 1200000
#define SCAN_BLOCKS 391  // ceil(NN/256)

// ---------------- device scratch ----------------
__device__ __half d_g[NN * HID];    // dis-scaled per-node messages (fp16)
__device__ float d_accA[NN * HID];
__device__ float d_accB[NN * HID];
__device__ float d_dis[NN];
__device__ int   d_deg[NN];
__device__ int   d_off[NN];
__device__ int   d_cur[NN];
__device__ int   d_csr[MAXE];
__device__ int   d_bsum[512];
__device__ int   d_bbase[512];
__device__ float d_sumIn[IND], d_sqIn[IND], d_ain[IND], d_cin[IND];
__device__ float d_sumL[3 * HID], d_sqL[3 * HID];
__device__ float d_pool[NG * HID];
__device__ int   d_cnt[NG];

// ---------------- f32x2 helpers ----------------
__device__ __forceinline__ unsigned long long pk2(float x) {
    unsigned long long r;
    asm("mov.b64 %0,{%1,%1};" : "=l"(r) : "f"(x));
    return r;
}
__device__ __forceinline__ void fma2(unsigned long long& d, unsigned long long a,
                                     unsigned long long b) {
    asm("fma.rn.f32x2 %0,%1,%2,%0;" : "+l"(d) : "l"(a), "l"(b));
}
__device__ __forceinline__ void unpk2(unsigned long long v, float& a, float& b) {
    asm("mov.b64 {%0,%1},%2;" : "=f"(a), "=f"(b) : "l"(v));
}

// ---------------- init ----------------
__global__ void k_zero() {
    int i = blockIdx.x * 256 + threadIdx.x;
    if (i < NN) d_deg[i] = 0;
    if (i < NG * HID) d_pool[i] = 0.f;
    if (i < NG) d_cnt[i] = 0;
    if (i < 3 * HID) { d_sumL[i] = 0.f; d_sqL[i] = 0.f; }
    if (i < IND) { d_sumIn[i] = 0.f; d_sqIn[i] = 0.f; }
}

__global__ void k_deg(const int* __restrict__ dst, int E) {
    int e = blockIdx.x * 256 + threadIdx.x;
    if (e < E) atomicAdd(&d_deg[dst[e]], 1);
}

// ---------------- input batchnorm stats over x [N,16] ----------------
__global__ void k_statsIn(const float* __restrict__ x) {
    int col = threadIdx.x & 15, grp = threadIdx.x >> 4;
    float s = 0.f, q = 0.f;
    for (int row = blockIdx.x * 16 + grp; row < NN; row += gridDim.x * 16) {
        float v = x[row * IND + col];
        s += v; q += v * v;
    }
    __shared__ float ss[16][16], qq[16][16];
    ss[grp][col] = s; qq[grp][col] = q;
    __syncthreads();
    if (grp == 0) {
        for (int j = 1; j < 16; j++) { s += ss[j][col]; q += qq[j][col]; }
        atomicAdd(&d_sumIn[col], s);
        atomicAdd(&d_sqIn[col], q);
    }
}

// ---------------- dis + input-BN fold (runs on side stream) ----------------
__global__ void k_fin(const float* __restrict__ bng, const float* __restrict__ bnb) {
    int i = blockIdx.x * 256 + threadIdx.x;
    if (i < NN) d_dis[i] = rsqrtf((float)d_deg[i] + 1.0f);
    if (i < IND) {
        float m = d_sumIn[i] * (1.0f / NN);
        float v = d_sqIn[i] * (1.0f / NN) - m * m;
        float a = bng[i] * rsqrtf(v + EPS);
        d_ain[i] = a;
        d_cin[i] = bnb[i] - m * a;
    }
}

// ---------------- prefix scan of deg (warp-shuffle) ----------------
__global__ void k_scan1() {
    __shared__ int wsum[8];
    int tid = threadIdx.x;
    int lane = tid & 31, wid = tid >> 5;
    int i = blockIdx.x * 256 + tid;
    int v = (i < NN) ? d_deg[i] : 0;
    int s = v;
#pragma unroll
    for (int o = 1; o < 32; o <<= 1) {
        int t = __shfl_up_sync(0xffffffffu, s, o);
        if (lane >= o) s += t;
    }
    if (lane == 31) wsum[wid] = s;
    __syncthreads();
    if (wid == 0 && lane < 8) {
        int w = wsum[lane];
#pragma unroll
        for (int o = 1; o < 8; o <<= 1) {
            int t = __shfl_up_sync(0xffu, w, o);
            if (lane >= o) w += t;
        }
        wsum[lane] = w;
    }
    __syncthreads();
    int base = (wid > 0) ? wsum[wid - 1] : 0;
    if (i < NN) d_off[i] = base + s - v;  // exclusive
    if (tid == 255) d_bsum[blockIdx.x] = wsum[7];
}

__global__ void k_scan2() {
    __shared__ int wsum[16];
    int tid = threadIdx.x;
    int lane = tid & 31, wid = tid >> 5;
    int v = (tid < SCAN_BLOCKS) ? d_bsum[tid] : 0;
    int s = v;
#pragma unroll
    for (int o = 1; o < 32; o <<= 1) {
        int t = __shfl_up_sync(0xffffffffu, s, o);
        if (lane >= o) s += t;
    }
    if (lane == 31) wsum[wid] = s;
    __syncthreads();
    if (wid == 0 && lane < 16) {
        int w = wsum[lane];
#pragma unroll
        for (int o = 1; o < 16; o <<= 1) {
            int t = __shfl_up_sync(0xffffu, w, o);
            if (lane >= o) w += t;
        }
        wsum[lane] = w;
    }
    __syncthreads();
    int base = (wid > 0) ? wsum[wid - 1] : 0;
    if (tid < SCAN_BLOCKS) d_bbase[tid] = base + s - v;  // exclusive
}

__global__ void k_scan3() {
    int i = blockIdx.x * 256 + threadIdx.x;
    if (i < NN) {
        d_off[i] += d_bbase[i >> 8];
        d_cur[i] = 0;
    }
}

__global__ void k_fill(const int* __restrict__ src, const int* __restrict__ dst, int E) {
    int e = blockIdx.x * 256 + threadIdx.x;
    if (e >= E) return;
    int d = dst[e];
    int pos = atomicAdd(&d_cur[d], 1);
    d_csr[d_off[d] + pos] = src[e];
}

// ---------------- GEMM: g[row] = fp16( dis[row] * (T(in[row]) @ W) ) ----------------
// 128 threads/block, 128 rows/block, 8 rows x 8 cols per thread.
// MODE 0: T = ain[k]*x + cin[k]
// MODE 1: T = relu(in*scl[k] + shf[k]), scl/shf computed per-block from stats.
template <int K, int MODE>
__global__ void __launch_bounds__(128) k_gemm(const float* __restrict__ in,
                                              const float* __restrict__ W,
                                              __half* __restrict__ gOut,
                                              const float* __restrict__ sumL,
                                              const float* __restrict__ sqL,
                                              const float* __restrict__ gam,
                                              const float* __restrict__ bet) {
    constexpr int CHUNK = (K < 32) ? K : 32;
    constexpr int NCH = K / CHUNK;
    constexpr int SH = (CHUNK == 16) ? 4 : 5;
    __shared__ __align__(16) float Wsh[K * 64];
    __shared__ __align__(16) float ins[CHUNK * 132];
    __shared__ float sA[64], sC[64];
    const int tid = threadIdx.x;
    const int c0 = (tid & 7) * 8;
    const int r0 = (tid >> 3) * 8;

    for (int i = tid; i < K * 64; i += 128) Wsh[i] = W[i];
    if (MODE == 0) {
        if (tid < K) { sA[tid] = d_ain[tid]; sC[tid] = d_cin[tid]; }
    } else {
        if (tid < 64) {
            float m = sumL[tid] * (1.0f / NN);
            float var = sqL[tid] * (1.0f / NN) - m * m;
            float s = gam[tid] * rsqrtf(var + EPS);
            sA[tid] = s;
            sC[tid] = bet[tid] - m * s;
        }
    }

    const int rowBase = blockIdx.x * 128;
    const int kk = tid & (CHUNK - 1);
    unsigned long long acc[8][4];
#pragma unroll
    for (int r = 0; r < 8; r++)
#pragma unroll
        for (int c = 0; c < 4; c++) acc[r][c] = 0ull;

    for (int kc = 0; kc < NCH; kc++) {
        __syncthreads();
        const int kg = kc * CHUNK + kk;
        const float t_a = sA[kg], t_c = sC[kg];
        for (int i = tid; i < 128 * CHUNK; i += 128) {
            int rl = i >> SH;
            int row = rowBase + rl;
            float v = 0.f;
            if (row < NN) {
                float u = in[(size_t)row * K + kg];
                if (MODE == 0) v = fmaf(t_a, u, t_c);
                else           v = fmaxf(fmaf(u, t_a, t_c), 0.f);
            }
            ins[kk * 132 + rl] = v;
        }
        __syncthreads();
#pragma unroll
        for (int k = 0; k < CHUNK; k++) {
            const float* wrow = Wsh + (kc * CHUNK + k) * 64;
            ulonglong2 wa = *(const ulonglong2*)(wrow + c0);
            ulonglong2 wb = *(const ulonglong2*)(wrow + c0 + 4);
            const float* vrow = ins + k * 132;
            float4 va = *(const float4*)(vrow + r0);
            float4 vb = *(const float4*)(vrow + r0 + 4);
            unsigned long long p[8] = {pk2(va.x), pk2(va.y), pk2(va.z), pk2(va.w),
                                       pk2(vb.x), pk2(vb.y), pk2(vb.z), pk2(vb.w)};
#pragma unroll
            for (int r = 0; r < 8; r++) {
                fma2(acc[r][0], p[r], wa.x);
                fma2(acc[r][1], p[r], wa.y);
                fma2(acc[r][2], p[r], wb.x);
                fma2(acc[r][3], p[r], wb.y);
            }
        }
    }

#pragma unroll
    for (int r = 0; r < 8; r++) {
        int row = rowBase + r0 + r;
        if (row < NN) {
            float dr = d_dis[row];
            float f0, f1, f2, f3, f4, f5, f6, f7;
            unpk2(acc[r][0], f0, f1);
            unpk2(acc[r][1], f2, f3);
            unpk2(acc[r][2], f4, f5);
            unpk2(acc[r][3], f6, f7);
            __half2 h0 = __floats2half2_rn(f0 * dr, f1 * dr);
            __half2 h1 = __floats2half2_rn(f2 * dr, f3 * dr);
            __half2 h2 = __floats2half2_rn(f4 * dr, f5 * dr);
            __half2 h3 = __floats2half2_rn(f6 * dr, f7 * dr);
            uint4 u;
            u.x = *(unsigned*)&h0; u.y = *(unsigned*)&h1;
            u.z = *(unsigned*)&h2; u.w = *(unsigned*)&h3;
            *(uint4*)(gOut + (size_t)row * 64 + c0) = u;  // 16B aligned (c0 mult of 8)
        }
    }
}

// ---------------- CSR aggregation (fp16 gather) + dis-scale + fused BN stats ----
// Each uint2 = 4 halfs; tx in 0..15 covers 64 features.
__global__ void __launch_bounds__(256) k_agg(const uint2* __restrict__ g2,
                                             float4* __restrict__ acc4,
                                             float* __restrict__ sumOut,
                                             float* __restrict__ sqOut) {
    __shared__ float ssum[64], ssq[64];
    const int tx = threadIdx.x, ty = threadIdx.y;
    const int tid = ty * 16 + tx;
    if (tid < 64) { ssum[tid] = 0.f; ssq[tid] = 0.f; }
    __syncthreads();

    float psx = 0.f, psy = 0.f, psz = 0.f, psw = 0.f;
    float pqx = 0.f, pqy = 0.f, pqz = 0.f, pqw = 0.f;
    const int base = blockIdx.x * 64 + ty * 4;
#pragma unroll
    for (int r = 0; r < 4; r++) {
        int n = base + r;
        if (n >= NN) break;
        uint2 us = __ldg(g2 + (size_t)n * 16 + tx);  // self-loop term
        float2 fa = __half22float2(*(__half2*)&us.x);
        float2 fb = __half22float2(*(__half2*)&us.y);
        float4 a = make_float4(fa.x, fa.y, fb.x, fb.y);
        int beg = d_off[n];
        int cnt = d_deg[n];
        int e = 0;
        for (; e + 4 <= cnt; e += 4) {
            int s0 = __ldg(d_csr + beg + e);
            int s1 = __ldg(d_csr + beg + e + 1);
            int s2 = __ldg(d_csr + beg + e + 2);
            int s3 = __ldg(d_csr + beg + e + 3);
            uint2 u0 = __ldg(g2 + (size_t)s0 * 16 + tx);
            uint2 u1 = __ldg(g2 + (size_t)s1 * 16 + tx);
            uint2 u2 = __ldg(g2 + (size_t)s2 * 16 + tx);
            uint2 u3 = __ldg(g2 + (size_t)s3 * 16 + tx);
            float2 a0 = __half22float2(*(__half2*)&u0.x), b0 = __half22float2(*(__half2*)&u0.y);
            float2 a1 = __half22float2(*(__half2*)&u1.x), b1 = __half22float2(*(__half2*)&u1.y);
            float2 a2 = __half22float2(*(__half2*)&u2.x), b2 = __half22float2(*(__half2*)&u2.y);
            float2 a3 = __half22float2(*(__half2*)&u3.x), b3 = __half22float2(*(__half2*)&u3.y);
            a.x += (a0.x + a1.x) + (a2.x + a3.x);
            a.y += (a0.y + a1.y) + (a2.y + a3.y);
            a.z += (b0.x + b1.x) + (b2.x + b3.x);
            a.w += (b0.y + b1.y) + (b2.y + b3.y);
        }
        for (; e < cnt; e++) {
            int s = __ldg(d_csr + beg + e);
            uint2 u = __ldg(g2 + (size_t)s * 16 + tx);
            float2 va = __half22float2(*(__half2*)&u.x);
            float2 vb = __half22float2(*(__half2*)&u.y);
            a.x += va.x; a.y += va.y; a.z += vb.x; a.w += vb.y;
        }
        float dr = d_dis[n];
        a.x *= dr; a.y *= dr; a.z *= dr; a.w *= dr;
        acc4[(size_t)n * 16 + tx] = a;
        psx += a.x; psy += a.y; psz += a.z; psw += a.w;
        pqx += a.x * a.x; pqy += a.y * a.y; pqz += a.z * a.z; pqw += a.w * a.w;
    }
    int c0 = tx * 4;
    atomicAdd(&ssum[c0 + 0], psx); atomicAdd(&ssq[c0 + 0], pqx);
    atomicAdd(&ssum[c0 + 1], psy); atomicAdd(&ssq[c0 + 1], pqy);
    atomicAdd(&ssum[c0 + 2], psz); atomicAdd(&ssq[c0 + 2], pqz);
    atomicAdd(&ssum[c0 + 3], psw); atomicAdd(&ssq[c0 + 3], pqw);
    __syncthreads();
    if (tid < 64) {
        atomicAdd(sumOut + tid, ssum[tid]);
        atomicAdd(sqOut + tid, ssq[tid]);
    }
}

// ---------------- final activation + mean-pool scatter (fused layer-3 BN fold) ----
__global__ void k_pool(const float4* __restrict__ acc4, const int* __restrict__ bids,
                       const float* __restrict__ sumL, const float* __restrict__ sqL,
                       const float* __restrict__ gam, const float* __restrict__ bet) {
    __shared__ float sA[64], sC[64];
    int tid = threadIdx.x;
    if (tid < 64) {
        float m = sumL[tid] * (1.0f / NN);
        float var = sqL[tid] * (1.0f / NN) - m * m;
        float s = gam[tid] * rsqrtf(var + EPS);
        sA[tid] = s;
        sC[tid] = bet[tid] - m * s;
    }
    __syncthreads();
    int t = blockIdx.x * 256 + tid;
    int node = t >> 4, c = t & 15;
    if (node >= NN) return;
    int gph = __ldg(bids + node);
    float4 v = __ldg(acc4 + (size_t)node * 16 + c);
    int cb = c * 4;
    float4 o;
    o.x = fmaxf(fmaf(v.x, sA[cb + 0], sC[cb + 0]), 0.f);
    o.y = fmaxf(fmaf(v.y, sA[cb + 1], sC[cb + 1]), 0.f);
    o.z = fmaxf(fmaf(v.z, sA[cb + 2], sC[cb + 2]), 0.f);
    o.w = fmaxf(fmaf(v.w, sA[cb + 3], sC[cb + 3]), 0.f);
    float* p = d_pool + (size_t)gph * HID + cb;
    asm volatile("red.global.add.v4.f32 [%0], {%1,%2,%3,%4};"
                 :: "l"(p), "f"(o.x), "f"(o.y), "f"(o.z), "f"(o.w) : "memory");
    if (c == 0) atomicAdd(&d_cnt[gph], 1);
}

// ---------------- classifier head ----------------
__global__ void k_head(const float* __restrict__ Wc1, const float* __restrict__ bc1,
                       const float* __restrict__ Wc2, const float* __restrict__ bc2,
                       float* __restrict__ out) {
    int g = blockIdx.x, t = threadIdx.x;
    __shared__ float p[64], z[64];
    float cnt = fmaxf((float)d_cnt[g], 1.0f);
    p[t] = d_pool[g * 64 + t] / cnt;
    __syncthreads();
    float a = bc1[t];
#pragma unroll
    for (int k = 0; k < 64; k++) a = fmaf(p[k], Wc1[k * 64 + t], a);
    z[t] = fmaxf(a, 0.f);
    __syncthreads();
    if (t < 2) {
        float o = bc2[t];
#pragma unroll
        for (int k = 0; k < 64; k++) o = fmaf(z[k], Wc2[k * 2 + t], o);
        out[g * 2 + t] = o;
    }
}

// ---------------- launch ----------------
extern "C" void kernel_launch(void* const* d_in, const int* in_sizes, int n_in,
                              void* d_out, int out_size) {
    const float *x = nullptr, *bn_in_g = nullptr, *bn_in_b = nullptr;
    const float *W0 = nullptr, *W1 = nullptr, *W2 = nullptr, *Wc1 = nullptr, *Wc2 = nullptr;
    const float *sz64[10] = {nullptr};
    const float *bc2 = nullptr;
    const int *eidx = nullptr, *bids = nullptr;
    int E = 1200000;
    int c64 = 0, c4096 = 0, c16 = 0;
    for (int i = 0; i < n_in; i++) {
        int s = in_sizes[i];
        const void* p = d_in[i];
        switch (s) {
            case 1600000: x = (const float*)p; break;
            case 2400000: eidx = (const int*)p; E = s / 2; break;
            case 100000:  bids = (const int*)p; break;
            case 16:   if (c16++ == 0) bn_in_g = (const float*)p; else bn_in_b = (const float*)p; break;
            case 1024: W0 = (const float*)p; break;
            case 4096:
                if (c4096 == 0) W1 = (const float*)p;
                else if (c4096 == 1) W2 = (const float*)p;
                else Wc1 = (const float*)p;
                c4096++; break;
            case 64:  if (c64 < 10) sz64[c64] = (const float*)p; c64++; break;
            case 128: Wc2 = (const float*)p; break;
            case 2:   bc2 = (const float*)p; break;
            default: break;
        }
    }
    const float *g0 = sz64[1], *be0 = sz64[2];
    const float *g1 = sz64[4], *be1 = sz64[5];
    const float *g2 = sz64[7], *be2 = sz64[8];
    const float *bc1 = sz64[9];
    const int* srcA = eidx;
    const int* dstA = eidx + E;
    float* out = (float*)d_out;

    __half* p_g;
    float *p_accA, *p_accB, *p_sumL, *p_sqL;
    cudaGetSymbolAddress((void**)&p_g, d_g);
    cudaGetSymbolAddress((void**)&p_accA, d_accA);
    cudaGetSymbolAddress((void**)&p_accB, d_accB);
    cudaGetSymbolAddress((void**)&p_sumL, d_sumL);
    cudaGetSymbolAddress((void**)&p_sqL, d_sqL);

    static cudaStream_t s2 = nullptr;
    static cudaEvent_t ev1 = nullptr, ev2 = nullptr;
    if (!s2) {
        cudaStreamCreateWithFlags(&s2, cudaStreamNonBlocking);
        cudaEventCreateWithFlags(&ev1, cudaEventDisableTiming);
        cudaEventCreateWithFlags(&ev2, cudaEventDisableTiming);
    }

    const int ZG = SCAN_BLOCKS;
    const int EG = (E + 255) / 256;
    const int GG = (NN + 127) / 128;  // 782
    const int AG = (NN + 63) / 64;    // 1563
    dim3 ablk(16, 16);

    k_zero<<<ZG, 256>>>();
    k_deg<<<EG, 256>>>(dstA, E);

    // fork: BN-stats + input-fold + layer-1 GEMM overlap the CSR build
    cudaEventRecord(ev1, 0);
    cudaStreamWaitEvent(s2, ev1, 0);
    k_statsIn<<<256, 256, 0, s2>>>(x);
    k_fin<<<ZG, 256, 0, s2>>>(bn_in_g, bn_in_b);
    k_gemm<16, 0><<<GG, 128, 0, s2>>>(x, W0, p_g, nullptr, nullptr, nullptr, nullptr);
    cudaEventRecord(ev2, s2);

    k_scan1<<<ZG, 256>>>();
    k_scan2<<<1, 512>>>();
    k_scan3<<<ZG, 256>>>();
    k_fill<<<EG, 256>>>(srcA, dstA, E);

    cudaStreamWaitEvent(0, ev2, 0);  // join

    // Layer 1 aggregation
    k_agg<<<AG, ablk>>>((const uint2*)p_g, (float4*)p_accA, p_sumL + 0, p_sqL + 0);
    // Layer 2
    k_gemm<64, 1><<<GG, 128>>>(p_accA, W1, p_g, p_sumL + 0, p_sqL + 0, g0, be0);
    k_agg<<<AG, ablk>>>((const uint2*)p_g, (float4*)p_accB, p_sumL + 64, p_sqL + 64);
    // Layer 3
    k_gemm<64, 1><<<GG, 128>>>(p_accB, W2, p_g, p_sumL + 64, p_sqL + 64, g1, be1);
    k_agg<<<AG, ablk>>>((const uint2*)p_g, (float4*)p_accA, p_sumL + 128, p_sqL + 128);

    // Pool (fused layer-3 BN fold) + head
    k_pool<<<(NN * 16 + 255) / 256, 256>>>((const float4*)p_accA, bids,
                                           p_sumL + 128, p_sqL + 128, g2, be2);
    k_head<<<NG, 64>>>(Wc1, bc1, Wc2, bc2, out);
}

// round 8
// speedup vs baseline: 2.0338x; 1.1513x over previous
#include <cuda_runtime.h>
#include <cuda_fp16.h>
#include <cstdint>

#define NN 100000
#define NG 512
#define IND 16
#define HID 64
#define EPS 1e-5f
#define MAXE 1200000
#define SCAN_BLOCKS 391  // ceil(NN/256)

// ---------------- device scratch ----------------
__device__ __half d_g[NN * HID];     // dis-scaled per-node messages (fp16)
__device__ __half d_accA[NN * HID];  // aggregated features (fp16)
__device__ __half d_accB[NN * HID];
__device__ int   d_deg[NN];
__device__ int   d_off[NN];
__device__ int   d_cur[NN];
__device__ int   d_csr[MAXE];
__device__ int   d_bsum[512];
__device__ int   d_bbase[512];
__device__ float d_sumIn[IND], d_sqIn[IND];
__device__ float d_sumL[3 * HID], d_sqL[3 * HID];
__device__ float d_pool[NG * HID];
__device__ int   d_cnt[NG];

// ---------------- f32x2 helpers ----------------
__device__ __forceinline__ unsigned long long pk2(float x) {
    unsigned long long r;
    asm("mov.b64 %0,{%1,%1};" : "=l"(r) : "f"(x));
    return r;
}
__device__ __forceinline__ void fma2(unsigned long long& d, unsigned long long a,
                                     unsigned long long b) {
    asm("fma.rn.f32x2 %0,%1,%2,%0;" : "+l"(d) : "l"(a), "l"(b));
}
__device__ __forceinline__ void unpk2(unsigned long long v, float& a, float& b) {
    asm("mov.b64 {%0,%1},%2;" : "=f"(a), "=f"(b) : "l"(v));
}

// ---------------- init ----------------
__global__ void k_zero() {
    int i = blockIdx.x * 256 + threadIdx.x;
    if (i < NN) { d_deg[i] = 0; d_cur[i] = 0; }
    if (i < NG * HID) d_pool[i] = 0.f;
    if (i < NG) d_cnt[i] = 0;
    if (i < 3 * HID) { d_sumL[i] = 0.f; d_sqL[i] = 0.f; }
    if (i < IND) { d_sumIn[i] = 0.f; d_sqIn[i] = 0.f; }
}

__global__ void k_deg(const int* __restrict__ dst, int E) {
    int e = blockIdx.x * 256 + threadIdx.x;
    if (e < E) atomicAdd(&d_deg[dst[e]], 1);
}

// ---------------- input batchnorm stats over x [N,16] ----------------
__global__ void k_statsIn(const float* __restrict__ x) {
    int col = threadIdx.x & 15, grp = threadIdx.x >> 4;
    float s = 0.f, q = 0.f;
    for (int row = blockIdx.x * 16 + grp; row < NN; row += gridDim.x * 16) {
        float v = x[row * IND + col];
        s += v; q += v * v;
    }
    __shared__ float ss[16][16], qq[16][16];
    ss[grp][col] = s; qq[grp][col] = q;
    __syncthreads();
    if (grp == 0) {
        for (int j = 1; j < 16; j++) { s += ss[j][col]; q += qq[j][col]; }
        atomicAdd(&d_sumIn[col], s);
        atomicAdd(&d_sqIn[col], q);
    }
}

// ---------------- prefix scan of deg (warp-shuffle) ----------------
__global__ void k_scan1() {
    __shared__ int wsum[8];
    int tid = threadIdx.x;
    int lane = tid & 31, wid = tid >> 5;
    int i = blockIdx.x * 256 + tid;
    int v = (i < NN) ? d_deg[i] : 0;
    int s = v;
#pragma unroll
    for (int o = 1; o < 32; o <<= 1) {
        int t = __shfl_up_sync(0xffffffffu, s, o);
        if (lane >= o) s += t;
    }
    if (lane == 31) wsum[wid] = s;
    __syncthreads();
    if (wid == 0 && lane < 8) {
        int w = wsum[lane];
#pragma unroll
        for (int o = 1; o < 8; o <<= 1) {
            int t = __shfl_up_sync(0xffu, w, o);
            if (lane >= o) w += t;
        }
        wsum[lane] = w;
    }
    __syncthreads();
    int base = (wid > 0) ? wsum[wid - 1] : 0;
    if (i < NN) d_off[i] = base + s - v;  // exclusive within block
    if (tid == 255) d_bsum[blockIdx.x] = wsum[7];
}

__global__ void k_scan2() {
    __shared__ int wsum[16];
    int tid = threadIdx.x;
    int lane = tid & 31, wid = tid >> 5;
    int v = (tid < SCAN_BLOCKS) ? d_bsum[tid] : 0;
    int s = v;
#pragma unroll
    for (int o = 1; o < 32; o <<= 1) {
        int t = __shfl_up_sync(0xffffffffu, s, o);
        if (lane >= o) s += t;
    }
    if (lane == 31) wsum[wid] = s;
    __syncthreads();
    if (wid == 0 && lane < 16) {
        int w = wsum[lane];
#pragma unroll
        for (int o = 1; o < 16; o <<= 1) {
            int t = __shfl_up_sync(0xffffu, w, o);
            if (lane >= o) w += t;
        }
        wsum[lane] = w;
    }
    __syncthreads();
    int base = (wid > 0) ? wsum[wid - 1] : 0;
    if (tid < 512) d_bbase[tid] = (tid < SCAN_BLOCKS) ? (base + s - v) : 0;  // exclusive
}

__global__ void k_fill(const int* __restrict__ src, const int* __restrict__ dst, int E) {
    int e = blockIdx.x * 256 + threadIdx.x;
    if (e >= E) return;
    int d = dst[e];
    int o = d_off[d] + d_bbase[d >> 8];
    int pos = atomicAdd(&d_cur[d], 1);
    d_csr[o + pos] = src[e];
}

// ---------------- GEMM: g[row] = fp16( dis[row] * (T(in[row]) @ W) ) ----------------
// 128 threads/block, 128 rows/block, 8 rows x 8 cols per thread.
// MODE 0: in fp32 x; T = ain[k]*x + cin[k], ain/cin computed per-block from d_sumIn.
// MODE 1: in fp16 acc; T = relu(in*scl[k] + shf[k]), scl/shf per-block from layer stats.
template <int K, int MODE>
__global__ void __launch_bounds__(128) k_gemm(const void* __restrict__ inV,
                                              const float* __restrict__ W,
                                              __half* __restrict__ gOut,
                                              const float* __restrict__ sumL,
                                              const float* __restrict__ sqL,
                                              const float* __restrict__ gam,
                                              const float* __restrict__ bet) {
    constexpr int CHUNK = (K < 32) ? K : 32;
    constexpr int NCH = K / CHUNK;
    constexpr int SH = (CHUNK == 16) ? 4 : 5;
    __shared__ __align__(16) float Wsh[K * 64];
    __shared__ __align__(16) float ins[CHUNK * 132];
    __shared__ float sA[64], sC[64];
    const int tid = threadIdx.x;
    const int c0 = (tid & 7) * 8;
    const int r0 = (tid >> 3) * 8;

    for (int i = tid; i < K * 64; i += 128) Wsh[i] = W[i];
    if (MODE == 0) {
        if (tid < K) {
            float m = d_sumIn[tid] * (1.0f / NN);
            float var = d_sqIn[tid] * (1.0f / NN) - m * m;
            float a = gam[tid] * rsqrtf(var + EPS);
            sA[tid] = a;
            sC[tid] = bet[tid] - m * a;
        }
    } else {
        if (tid < 64) {
            float m = sumL[tid] * (1.0f / NN);
            float var = sqL[tid] * (1.0f / NN) - m * m;
            float s = gam[tid] * rsqrtf(var + EPS);
            sA[tid] = s;
            sC[tid] = bet[tid] - m * s;
        }
    }

    const int rowBase = blockIdx.x * 128;
    const int kk = tid & (CHUNK - 1);
    unsigned long long acc[8][4];
#pragma unroll
    for (int r = 0; r < 8; r++)
#pragma unroll
        for (int c = 0; c < 4; c++) acc[r][c] = 0ull;

    for (int kc = 0; kc < NCH; kc++) {
        __syncthreads();
        const int kg = kc * CHUNK + kk;
        const float t_a = sA[kg], t_c = sC[kg];
        for (int i = tid; i < 128 * CHUNK; i += 128) {
            int rl = i >> SH;
            int row = rowBase + rl;
            float v = 0.f;
            if (row < NN) {
                float u;
                if (MODE == 0) u = ((const float*)inV)[(size_t)row * K + kg];
                else           u = __half2float(((const __half*)inV)[(size_t)row * K + kg]);
                if (MODE == 0) v = fmaf(t_a, u, t_c);
                else           v = fmaxf(fmaf(u, t_a, t_c), 0.f);
            }
            ins[kk * 132 + rl] = v;
        }
        __syncthreads();
#pragma unroll
        for (int k = 0; k < CHUNK; k++) {
            const float* wrow = Wsh + (kc * CHUNK + k) * 64;
            ulonglong2 wa = *(const ulonglong2*)(wrow + c0);
            ulonglong2 wb = *(const ulonglong2*)(wrow + c0 + 4);
            const float* vrow = ins + k * 132;
            float4 va = *(const float4*)(vrow + r0);
            float4 vb = *(const float4*)(vrow + r0 + 4);
            unsigned long long p[8] = {pk2(va.x), pk2(va.y), pk2(va.z), pk2(va.w),
                                       pk2(vb.x), pk2(vb.y), pk2(vb.z), pk2(vb.w)};
#pragma unroll
            for (int r = 0; r < 8; r++) {
                fma2(acc[r][0], p[r], wa.x);
                fma2(acc[r][1], p[r], wa.y);
                fma2(acc[r][2], p[r], wb.x);
                fma2(acc[r][3], p[r], wb.y);
            }
        }
    }

#pragma unroll
    for (int r = 0; r < 8; r++) {
        int row = rowBase + r0 + r;
        if (row < NN) {
            float dr = rsqrtf((float)d_deg[row] + 1.0f);
            float f0, f1, f2, f3, f4, f5, f6, f7;
            unpk2(acc[r][0], f0, f1);
            unpk2(acc[r][1], f2, f3);
            unpk2(acc[r][2], f4, f5);
            unpk2(acc[r][3], f6, f7);
            __half2 h0 = __floats2half2_rn(f0 * dr, f1 * dr);
            __half2 h1 = __floats2half2_rn(f2 * dr, f3 * dr);
            __half2 h2 = __floats2half2_rn(f4 * dr, f5 * dr);
            __half2 h3 = __floats2half2_rn(f6 * dr, f7 * dr);
            uint4 u;
            u.x = *(unsigned*)&h0; u.y = *(unsigned*)&h1;
            u.z = *(unsigned*)&h2; u.w = *(unsigned*)&h3;
            *(uint4*)(gOut + (size_t)row * 64 + c0) = u;
        }
    }
}

// ---------------- CSR aggregation (fp16 gather) + dis-scale + fused BN stats ----
__global__ void __launch_bounds__(256) k_agg(const uint2* __restrict__ g2,
                                             uint2* __restrict__ accH,
                                             float* __restrict__ sumOut,
                                             float* __restrict__ sqOut) {
    __shared__ float ssum[64], ssq[64];
    const int tx = threadIdx.x, ty = threadIdx.y;
    const int tid = ty * 16 + tx;
    if (tid < 64) { ssum[tid] = 0.f; ssq[tid] = 0.f; }
    __syncthreads();

    float psx = 0.f, psy = 0.f, psz = 0.f, psw = 0.f;
    float pqx = 0.f, pqy = 0.f, pqz = 0.f, pqw = 0.f;
    const int base = blockIdx.x * 64 + ty * 4;
#pragma unroll
    for (int r = 0; r < 4; r++) {
        int n = base + r;
        if (n >= NN) break;
        uint2 us = __ldg(g2 + (size_t)n * 16 + tx);  // self-loop term
        float2 fa = __half22float2(*(__half2*)&us.x);
        float2 fb = __half22float2(*(__half2*)&us.y);
        float4 a = make_float4(fa.x, fa.y, fb.x, fb.y);
        int cnt = d_deg[n];
        int beg = d_off[n] + d_bbase[n >> 8];
        int e = 0;
        for (; e + 4 <= cnt; e += 4) {
            int s0 = __ldg(d_csr + beg + e);
            int s1 = __ldg(d_csr + beg + e + 1);
            int s2 = __ldg(d_csr + beg + e + 2);
            int s3 = __ldg(d_csr + beg + e + 3);
            uint2 u0 = __ldg(g2 + (size_t)s0 * 16 + tx);
            uint2 u1 = __ldg(g2 + (size_t)s1 * 16 + tx);
            uint2 u2 = __ldg(g2 + (size_t)s2 * 16 + tx);
            uint2 u3 = __ldg(g2 + (size_t)s3 * 16 + tx);
            float2 a0 = __half22float2(*(__half2*)&u0.x), b0 = __half22float2(*(__half2*)&u0.y);
            float2 a1 = __half22float2(*(__half2*)&u1.x), b1 = __half22float2(*(__half2*)&u1.y);
            float2 a2 = __half22float2(*(__half2*)&u2.x), b2 = __half22float2(*(__half2*)&u2.y);
            float2 a3 = __half22float2(*(__half2*)&u3.x), b3 = __half22float2(*(__half2*)&u3.y);
            a.x += (a0.x + a1.x) + (a2.x + a3.x);
            a.y += (a0.y + a1.y) + (a2.y + a3.y);
            a.z += (b0.x + b1.x) + (b2.x + b3.x);
            a.w += (b0.y + b1.y) + (b2.y + b3.y);
        }
        for (; e < cnt; e++) {
            int s = __ldg(d_csr + beg + e);
            uint2 u = __ldg(g2 + (size_t)s * 16 + tx);
            float2 va = __half22float2(*(__half2*)&u.x);
            float2 vb = __half22float2(*(__half2*)&u.y);
            a.x += va.x; a.y += va.y; a.z += vb.x; a.w += vb.y;
        }
        float dr = rsqrtf((float)cnt + 1.0f);
        a.x *= dr; a.y *= dr; a.z *= dr; a.w *= dr;
        __half2 h0 = __floats2half2_rn(a.x, a.y);
        __half2 h1 = __floats2half2_rn(a.z, a.w);
        uint2 uo;
        uo.x = *(unsigned*)&h0; uo.y = *(unsigned*)&h1;
        accH[(size_t)n * 16 + tx] = uo;
        psx += a.x; psy += a.y; psz += a.z; psw += a.w;
        pqx += a.x * a.x; pqy += a.y * a.y; pqz += a.z * a.z; pqw += a.w * a.w;
    }
    int c0 = tx * 4;
    atomicAdd(&ssum[c0 + 0], psx); atomicAdd(&ssq[c0 + 0], pqx);
    atomicAdd(&ssum[c0 + 1], psy); atomicAdd(&ssq[c0 + 1], pqy);
    atomicAdd(&ssum[c0 + 2], psz); atomicAdd(&ssq[c0 + 2], pqz);
    atomicAdd(&ssum[c0 + 3], psw); atomicAdd(&ssq[c0 + 3], pqw);
    __syncthreads();
    if (tid < 64) {
        atomicAdd(sumOut + tid, ssum[tid]);
        atomicAdd(sqOut + tid, ssq[tid]);
    }
}

// ---------------- final activation + run-accumulated mean-pool scatter ----------------
// batch_ids are sorted: thread owns 4 contiguous nodes, accumulates per-graph runs,
// flushes one red.v4 per run.
__global__ void __launch_bounds__(256) k_pool(const uint2* __restrict__ accH,
                                              const int* __restrict__ bids,
                                              const float* __restrict__ sumL,
                                              const float* __restrict__ sqL,
                                              const float* __restrict__ gam,
                                              const float* __restrict__ bet) {
    __shared__ float sA[64], sC[64];
    int tid = threadIdx.x;
    if (tid < 64) {
        float m = sumL[tid] * (1.0f / NN);
        float var = sqL[tid] * (1.0f / NN) - m * m;
        float s = gam[tid] * rsqrtf(var + EPS);
        sA[tid] = s;
        sC[tid] = bet[tid] - m * s;
    }
    __syncthreads();
    int tx = tid & 15, ty = tid >> 4;
    int cb = tx * 4;
    float a0 = sA[cb], a1 = sA[cb + 1], a2 = sA[cb + 2], a3 = sA[cb + 3];
    float c0v = sC[cb], c1v = sC[cb + 1], c2v = sC[cb + 2], c3v = sC[cb + 3];
    int base = blockIdx.x * 64 + ty * 4;
    int curG = -1, runLen = 0;
    float4 acc = make_float4(0.f, 0.f, 0.f, 0.f);
#pragma unroll
    for (int r = 0; r < 4; r++) {
        int n = base + r;
        if (n >= NN) break;
        int g = __ldg(bids + n);
        uint2 u = __ldg(accH + (size_t)n * 16 + tx);
        float2 va = __half22float2(*(__half2*)&u.x);
        float2 vb = __half22float2(*(__half2*)&u.y);
        float4 o;
        o.x = fmaxf(fmaf(va.x, a0, c0v), 0.f);
        o.y = fmaxf(fmaf(va.y, a1, c1v), 0.f);
        o.z = fmaxf(fmaf(vb.x, a2, c2v), 0.f);
        o.w = fmaxf(fmaf(vb.y, a3, c3v), 0.f);
        if (g != curG) {
            if (curG >= 0) {
                float* p = d_pool + (size_t)curG * HID + cb;
                asm volatile("red.global.add.v4.f32 [%0], {%1,%2,%3,%4};"
                             :: "l"(p), "f"(acc.x), "f"(acc.y), "f"(acc.z), "f"(acc.w)
                             : "memory");
                if (tx == 0) atomicAdd(&d_cnt[curG], runLen);
            }
            curG = g; acc = o; runLen = 1;
        } else {
            acc.x += o.x; acc.y += o.y; acc.z += o.z; acc.w += o.w;
            runLen++;
        }
    }
    if (curG >= 0) {
        float* p = d_pool + (size_t)curG * HID + cb;
        asm volatile("red.global.add.v4.f32 [%0], {%1,%2,%3,%4};"
                     :: "l"(p), "f"(acc.x), "f"(acc.y), "f"(acc.z), "f"(acc.w) : "memory");
        if (tx == 0) atomicAdd(&d_cnt[curG], runLen);
    }
}

// ---------------- classifier head ----------------
__global__ void k_head(const float* __restrict__ Wc1, const float* __restrict__ bc1,
                       const float* __restrict__ Wc2, const float* __restrict__ bc2,
                       float* __restrict__ out) {
    int g = blockIdx.x, t = threadIdx.x;
    __shared__ float p[64], z[64];
    float cnt = fmaxf((float)d_cnt[g], 1.0f);
    p[t] = d_pool[g * 64 + t] / cnt;
    __syncthreads();
    float a = bc1[t];
#pragma unroll
    for (int k = 0; k < 64; k++) a = fmaf(p[k], Wc1[k * 64 + t], a);
    z[t] = fmaxf(a, 0.f);
    __syncthreads();
    if (t < 2) {
        float o = bc2[t];
#pragma unroll
        for (int k = 0; k < 64; k++) o = fmaf(z[k], Wc2[k * 2 + t], o);
        out[g * 2 + t] = o;
    }
}

// ---------------- launch ----------------
extern "C" void kernel_launch(void* const* d_in, const int* in_sizes, int n_in,
                              void* d_out, int out_size) {
    const float *x = nullptr, *bn_in_g = nullptr, *bn_in_b = nullptr;
    const float *W0 = nullptr, *W1 = nullptr, *W2 = nullptr, *Wc1 = nullptr, *Wc2 = nullptr;
    const float *sz64[10] = {nullptr};
    const float *bc2 = nullptr;
    const int *eidx = nullptr, *bids = nullptr;
    int E = 1200000;
    int c64 = 0, c4096 = 0, c16 = 0;
    for (int i = 0; i < n_in; i++) {
        int s = in_sizes[i];
        const void* p = d_in[i];
        switch (s) {
            case 1600000: x = (const float*)p; break;
            case 2400000: eidx = (const int*)p; E = s / 2; break;
            case 100000:  bids = (const int*)p; break;
            case 16:   if (c16++ == 0) bn_in_g = (const float*)p; else bn_in_b = (const float*)p; break;
            case 1024: W0 = (const float*)p; break;
            case 4096:
                if (c4096 == 0) W1 = (const float*)p;
                else if (c4096 == 1) W2 = (const float*)p;
                else Wc1 = (const float*)p;
                c4096++; break;
            case 64:  if (c64 < 10) sz64[c64] = (const float*)p; c64++; break;
            case 128: Wc2 = (const float*)p; break;
            case 2:   bc2 = (const float*)p; break;
            default: break;
        }
    }
    const float *g0 = sz64[1], *be0 = sz64[2];
    const float *g1 = sz64[4], *be1 = sz64[5];
    const float *g2 = sz64[7], *be2 = sz64[8];
    const float *bc1 = sz64[9];
    const int* srcA = eidx;
    const int* dstA = eidx + E;
    float* out = (float*)d_out;

    __half *p_g, *p_accA, *p_accB;
    float *p_sumL, *p_sqL;
    cudaGetSymbolAddress((void**)&p_g, d_g);
    cudaGetSymbolAddress((void**)&p_accA, d_accA);
    cudaGetSymbolAddress((void**)&p_accB, d_accB);
    cudaGetSymbolAddress((void**)&p_sumL, d_sumL);
    cudaGetSymbolAddress((void**)&p_sqL, d_sqL);

    static cudaStream_t s2 = nullptr;
    static cudaEvent_t evZ = nullptr, evD = nullptr, ev2 = nullptr;
    if (!s2) {
        cudaStreamCreateWithFlags(&s2, cudaStreamNonBlocking);
        cudaEventCreateWithFlags(&evZ, cudaEventDisableTiming);
        cudaEventCreateWithFlags(&evD, cudaEventDisableTiming);
        cudaEventCreateWithFlags(&ev2, cudaEventDisableTiming);
    }

    const int ZG = SCAN_BLOCKS;
    const int EG = (E + 255) / 256;
    const int GG = (NN + 127) / 128;  // 782
    const int AG = (NN + 63) / 64;    // 1563
    dim3 ablk(16, 16);

    k_zero<<<ZG, 256>>>();
    cudaEventRecord(evZ, 0);
    k_deg<<<EG, 256>>>(dstA, E);
    cudaEventRecord(evD, 0);

    // side stream: BN stats (after zero) + layer-1 GEMM (after deg) overlap CSR build
    cudaStreamWaitEvent(s2, evZ, 0);
    k_statsIn<<<256, 256, 0, s2>>>(x);
    cudaStreamWaitEvent(s2, evD, 0);
    k_gemm<16, 0><<<GG, 128, 0, s2>>>(x, W0, p_g, nullptr, nullptr, bn_in_g, bn_in_b);
    cudaEventRecord(ev2, s2);

    k_scan1<<<ZG, 256>>>();
    k_scan2<<<1, 512>>>();
    k_fill<<<EG, 256>>>(srcA, dstA, E);

    cudaStreamWaitEvent(0, ev2, 0);  // join

    // Layer 1 aggregation
    k_agg<<<AG, ablk>>>((const uint2*)p_g, (uint2*)p_accA, p_sumL + 0, p_sqL + 0);
    // Layer 2
    k_gemm<64, 1><<<GG, 128>>>(p_accA, W1, p_g, p_sumL + 0, p_sqL + 0, g0, be0);
    k_agg<<<AG, ablk>>>((const uint2*)p_g, (uint2*)p_accB, p_sumL + 64, p_sqL + 64);
    // Layer 3
    k_gemm<64, 1><<<GG, 128>>>(p_accB, W2, p_g, p_sumL + 64, p_sqL + 64, g1, be1);
    k_agg<<<AG, ablk>>>((const uint2*)p_g, (uint2*)p_accA, p_sumL + 128, p_sqL + 128);

    // Pool (fused layer-3 BN fold, run-accumulated) + head
    k_pool<<<AG, 256>>>((const uint2*)p_accA, bids, p_sumL + 128, p_sqL + 128, g2, be2);
    k_head<<<NG, 64>>>(Wc1, bc1, Wc2, bc2, out);
}